// round 1
// baseline (speedup 1.0000x reference)
#include <cuda_runtime.h>
#include <cstdint>

#define N_NODES 100000
#define D_IN    500
#define D_H     128
#define D_O     64

// ---------------- scratch (device globals; no runtime allocation) ----------
__device__ float g_deg [N_NODES];
__device__ float g_dinv[N_NODES];
__device__ float g_h   [(size_t)N_NODES * D_H];   // x @ W1
__device__ float g_agg1[(size_t)N_NODES * D_H];   // aggregated + b1 (pre-relu)
__device__ float g_h3  [(size_t)N_NODES * D_O];   // relu(agg1) @ W2
__device__ float g_agg2[(size_t)N_NODES * D_O];   // z = aggregated + b2

// ---------------- degree / normalization ----------------
__global__ void deg_init_kernel() {
    int i = blockIdx.x * blockDim.x + threadIdx.x;
    if (i < N_NODES) g_deg[i] = 1.0f;   // self-loop contributes 1
}

__global__ void deg_count_kernel(const int* __restrict__ col, int E) {
    int e = blockIdx.x * blockDim.x + threadIdx.x;
    if (e < E) atomicAdd(&g_deg[col[e]], 1.0f);
}

__global__ void dinv_kernel() {
    int i = blockIdx.x * blockDim.x + threadIdx.x;
    if (i < N_NODES) g_dinv[i] = rsqrtf(g_deg[i]);
}

// ---------------- GEMM1: g_h = X[100000,500] @ W1[500,128] ----------------
// BM=128, BN=128, BK=25, 256 threads, 8x8 micro-tile, packed f32x2 FMAs.
__global__ void __launch_bounds__(256) gemm1_kernel(const float* __restrict__ X,
                                                    const float* __restrict__ W) {
    __shared__ float xs[25][132];   // transposed: xs[k][m], padded
    __shared__ float ws[25][128];   // ws[k][n]
    const int m0  = blockIdx.x * 128;
    const int tid = threadIdx.x;
    const int tx  = tid & 15;       // column group (8 cols)
    const int ty  = tid >> 4;       // row group (8 rows)

    unsigned long long acc[8][4];
    #pragma unroll
    for (int i = 0; i < 8; i++)
        #pragma unroll
        for (int j = 0; j < 4; j++) acc[i][j] = 0ULL;

    for (int k0 = 0; k0 < D_IN; k0 += 25) {
        // load X tile (128 x 25), store transposed
        #pragma unroll
        for (int it = 0; it < 13; it++) {
            int idx = tid + it * 256;
            if (idx < 3200) {
                int m = idx / 25, k = idx - m * 25;
                int gm = m0 + m;
                xs[k][m] = (gm < N_NODES) ? X[(size_t)gm * D_IN + k0 + k] : 0.0f;
            }
        }
        // load W tile (25 x 128)
        #pragma unroll
        for (int it = 0; it < 13; it++) {
            int idx = tid + it * 256;
            if (idx < 3200) {
                int k = idx >> 7, n = idx & 127;
                ws[k][n] = W[(size_t)(k0 + k) * D_H + n];
            }
        }
        __syncthreads();

        #pragma unroll
        for (int kk = 0; kk < 25; kk++) {
            float4 a0 = *(const float4*)&xs[kk][ty * 8];
            float4 a1 = *(const float4*)&xs[kk][ty * 8 + 4];
            float4 b0 = *(const float4*)&ws[kk][tx * 8];
            float4 b1 = *(const float4*)&ws[kk][tx * 8 + 4];
            unsigned long long bb[4];
            asm("mov.b64 %0, {%1,%2};" : "=l"(bb[0]) : "f"(b0.x), "f"(b0.y));
            asm("mov.b64 %0, {%1,%2};" : "=l"(bb[1]) : "f"(b0.z), "f"(b0.w));
            asm("mov.b64 %0, {%1,%2};" : "=l"(bb[2]) : "f"(b1.x), "f"(b1.y));
            asm("mov.b64 %0, {%1,%2};" : "=l"(bb[3]) : "f"(b1.z), "f"(b1.w));
            float av[8] = {a0.x, a0.y, a0.z, a0.w, a1.x, a1.y, a1.z, a1.w};
            #pragma unroll
            for (int i = 0; i < 8; i++) {
                unsigned long long aa;
                asm("mov.b64 %0, {%1,%1};" : "=l"(aa) : "f"(av[i]));
                #pragma unroll
                for (int j = 0; j < 4; j++)
                    asm("fma.rn.f32x2 %0, %1, %2, %0;"
                        : "+l"(acc[i][j]) : "l"(aa), "l"(bb[j]));
            }
        }
        __syncthreads();
    }

    #pragma unroll
    for (int i = 0; i < 8; i++) {
        int gm = m0 + ty * 8 + i;
        if (gm < N_NODES) {
            float lo0, hi0, lo1, hi1;
            asm("mov.b64 {%0,%1}, %2;" : "=f"(lo0), "=f"(hi0) : "l"(acc[i][0]));
            asm("mov.b64 {%0,%1}, %2;" : "=f"(lo1), "=f"(hi1) : "l"(acc[i][1]));
            float4 o0 = make_float4(lo0, hi0, lo1, hi1);
            asm("mov.b64 {%0,%1}, %2;" : "=f"(lo0), "=f"(hi0) : "l"(acc[i][2]));
            asm("mov.b64 {%0,%1}, %2;" : "=f"(lo1), "=f"(hi1) : "l"(acc[i][3]));
            float4 o1 = make_float4(lo0, hi0, lo1, hi1);
            *(float4*)&g_h[(size_t)gm * D_H + tx * 8]     = o0;
            *(float4*)&g_h[(size_t)gm * D_H + tx * 8 + 4] = o1;
        }
    }
}

// ---------------- agg1 init: self-loop + bias -------------
// agg1[i][:] = b1 + h[i][:] * dinv[i]^2
__global__ void agg1_init_kernel(const float* __restrict__ b1) {
    int idx = blockIdx.x * blockDim.x + threadIdx.x;   // over N*32 float4s
    if (idx >= N_NODES * 32) return;
    int node = idx >> 5;
    int j4   = idx & 31;
    float d  = g_dinv[node];
    float d2 = d * d;
    float4 h = *(const float4*)&g_h[(size_t)idx * 4];
    float4 b = *(const float4*)&b1[j4 * 4];
    float4 o = make_float4(fmaf(h.x, d2, b.x), fmaf(h.y, d2, b.y),
                           fmaf(h.z, d2, b.z), fmaf(h.w, d2, b.w));
    *(float4*)&g_agg1[(size_t)idx * 4] = o;
}

// ---------------- scatter1: one warp per edge, 128 floats ----------------
__global__ void scatter1_kernel(const int* __restrict__ ei, int E) {
    int t = blockIdx.x * blockDim.x + threadIdx.x;
    int e = t >> 5;
    int l = t & 31;
    if (e >= E) return;
    int r = ei[e];
    int c = ei[E + e];
    float nrm = g_dinv[r] * g_dinv[c];
    float4 v = *(const float4*)&g_h[(size_t)r * D_H + l * 4];
    float* dst = &g_agg1[(size_t)c * D_H + l * 4];
    asm volatile("red.global.add.v4.f32 [%0], {%1,%2,%3,%4};"
                 :: "l"(dst), "f"(v.x * nrm), "f"(v.y * nrm),
                    "f"(v.z * nrm), "f"(v.w * nrm) : "memory");
}

// ---------------- GEMM2: g_h3 = relu(g_agg1)[100000,128] @ W2[128,64] -----
// BM=128, BN=64, BK=32, 256 threads, 8x4 micro-tile (scalar fma)
__global__ void __launch_bounds__(256) gemm2_kernel(const float* __restrict__ W) {
    __shared__ float xs[32][132];   // transposed relu(A)
    __shared__ float ws[32][64];
    const int m0  = blockIdx.x * 128;
    const int tid = threadIdx.x;
    const int tx  = tid & 15;       // 4 cols each
    const int ty  = tid >> 4;       // 8 rows each

    float acc[8][4];
    #pragma unroll
    for (int i = 0; i < 8; i++)
        #pragma unroll
        for (int j = 0; j < 4; j++) acc[i][j] = 0.0f;

    for (int k0 = 0; k0 < D_H; k0 += 32) {
        #pragma unroll
        for (int it = 0; it < 16; it++) {
            int idx = tid + it * 256;         // 128*32 = 4096
            int m = idx >> 5, k = idx & 31;
            int gm = m0 + m;
            float v = (gm < N_NODES) ? g_agg1[(size_t)gm * D_H + k0 + k] : 0.0f;
            xs[k][m] = fmaxf(v, 0.0f);        // fused relu
        }
        #pragma unroll
        for (int it = 0; it < 8; it++) {
            int idx = tid + it * 256;         // 32*64 = 2048
            int k = idx >> 6, n = idx & 63;
            ws[k][n] = W[(size_t)(k0 + k) * D_O + n];
        }
        __syncthreads();

        #pragma unroll
        for (int kk = 0; kk < 32; kk++) {
            float4 a0 = *(const float4*)&xs[kk][ty * 8];
            float4 a1 = *(const float4*)&xs[kk][ty * 8 + 4];
            float4 b  = *(const float4*)&ws[kk][tx * 4];
            float av[8] = {a0.x, a0.y, a0.z, a0.w, a1.x, a1.y, a1.z, a1.w};
            float bv[4] = {b.x, b.y, b.z, b.w};
            #pragma unroll
            for (int i = 0; i < 8; i++)
                #pragma unroll
                for (int j = 0; j < 4; j++)
                    acc[i][j] = fmaf(av[i], bv[j], acc[i][j]);
        }
        __syncthreads();
    }

    #pragma unroll
    for (int i = 0; i < 8; i++) {
        int gm = m0 + ty * 8 + i;
        if (gm < N_NODES) {
            float4 o = make_float4(acc[i][0], acc[i][1], acc[i][2], acc[i][3]);
            *(float4*)&g_h3[(size_t)gm * D_O + tx * 4] = o;
        }
    }
}

// ---------------- agg2 init: self-loop + bias ----------------
__global__ void agg2_init_kernel(const float* __restrict__ b2) {
    int idx = blockIdx.x * blockDim.x + threadIdx.x;   // over N*16 float4s
    if (idx >= N_NODES * 16) return;
    int node = idx >> 4;
    int j4   = idx & 15;
    float d  = g_dinv[node];
    float d2 = d * d;
    float4 h = *(const float4*)&g_h3[(size_t)idx * 4];
    float4 b = *(const float4*)&b2[j4 * 4];
    float4 o = make_float4(fmaf(h.x, d2, b.x), fmaf(h.y, d2, b.y),
                           fmaf(h.z, d2, b.z), fmaf(h.w, d2, b.w));
    *(float4*)&g_agg2[(size_t)idx * 4] = o;
}

// ---------------- scatter2: 16 lanes per edge, 64 floats ----------------
__global__ void scatter2_kernel(const int* __restrict__ ei, int E) {
    int t = blockIdx.x * blockDim.x + threadIdx.x;
    int e = t >> 4;
    int l = t & 15;
    if (e >= E) return;
    int r = ei[e];
    int c = ei[E + e];
    float nrm = g_dinv[r] * g_dinv[c];
    float4 v = *(const float4*)&g_h3[(size_t)r * D_O + l * 4];
    float* dst = &g_agg2[(size_t)c * D_O + l * 4];
    asm volatile("red.global.add.v4.f32 [%0], {%1,%2,%3,%4};"
                 :: "l"(dst), "f"(v.x * nrm), "f"(v.y * nrm),
                    "f"(v.z * nrm), "f"(v.w * nrm) : "memory");
}

// ---------------- decode: scores[e] = dot(z[src], z[dst]) ----------------
__global__ void decode_kernel(const int* __restrict__ ei,
                              float* __restrict__ out, int E) {
    int t = blockIdx.x * blockDim.x + threadIdx.x;
    int e = t >> 4;
    int l = t & 15;
    if (e >= E) return;
    int a = ei[e];
    int b = ei[E + e];
    float4 va = *(const float4*)&g_agg2[(size_t)a * D_O + l * 4];
    float4 vb = *(const float4*)&g_agg2[(size_t)b * D_O + l * 4];
    float s = va.x * vb.x + va.y * vb.y + va.z * vb.z + va.w * vb.w;
    unsigned mask = __activemask();
    s += __shfl_xor_sync(mask, s, 1);
    s += __shfl_xor_sync(mask, s, 2);
    s += __shfl_xor_sync(mask, s, 4);
    s += __shfl_xor_sync(mask, s, 8);
    if (l == 0) out[e] = s;
}

// ---------------- launch ----------------
extern "C" void kernel_launch(void* const* d_in, const int* in_sizes, int n_in,
                              void* d_out, int out_size) {
    const float* x  = (const float*)d_in[0];
    const float* W1 = (const float*)d_in[1];
    const float* b1 = (const float*)d_in[2];
    const float* W2 = (const float*)d_in[3];
    const float* b2 = (const float*)d_in[4];
    const int*   ei = (const int*)d_in[5];
    const int E = in_sizes[5] / 2;

    deg_init_kernel<<<(N_NODES + 255) / 256, 256>>>();
    deg_count_kernel<<<(E + 255) / 256, 256>>>(ei + E, E);
    dinv_kernel<<<(N_NODES + 255) / 256, 256>>>();

    gemm1_kernel<<<(N_NODES + 127) / 128, 256>>>(x, W1);
    agg1_init_kernel<<<(N_NODES * 32 + 255) / 256, 256>>>(b1);
    scatter1_kernel<<<(int)(((long long)E * 32 + 255) / 256), 256>>>(ei, E);

    gemm2_kernel<<<(N_NODES + 127) / 128, 256>>>(W2);
    agg2_init_kernel<<<(N_NODES * 16 + 255) / 256, 256>>>(b2);
    scatter2_kernel<<<(int)(((long long)E * 16 + 255) / 256), 256>>>(ei, E);

    decode_kernel<<<(int)(((long long)E * 16 + 255) / 256), 256>>>(ei, (float*)d_out, E);
}

// round 2
// speedup vs baseline: 1.1238x; 1.1238x over previous
#include <cuda_runtime.h>
#include <cstdint>

#define N_NODES 100000
#define D_IN    500
#define D_H     128
#define D_O     64

// ---------------- scratch (device globals; no runtime allocation) ----------
__device__ float g_deg [N_NODES];
__device__ float g_dinv[N_NODES];
__device__ float g_h   [(size_t)N_NODES * D_H];   // x @ W1
__device__ float g_agg1[(size_t)N_NODES * D_H];   // aggregated + b1 (pre-relu)
__device__ float g_h3  [(size_t)N_NODES * D_O];   // relu(agg1) @ W2
__device__ float g_agg2[(size_t)N_NODES * D_O];   // z = aggregated + b2

// ---------------- degree / normalization ----------------
__global__ void deg_init_kernel() {
    int i = blockIdx.x * blockDim.x + threadIdx.x;
    if (i < N_NODES) g_deg[i] = 1.0f;   // self-loop contributes 1
}

__global__ void deg_count_kernel(const int* __restrict__ col, int E) {
    int e = blockIdx.x * blockDim.x + threadIdx.x;
    if (e < E) atomicAdd(&g_deg[col[e]], 1.0f);
}

__global__ void dinv_kernel() {
    int i = blockIdx.x * blockDim.x + threadIdx.x;
    if (i < N_NODES) g_dinv[i] = rsqrtf(g_deg[i]);
}

// ---------------- GEMM1: g_h = X[100000,500] @ W1[500,128] ----------------
// BM=128, BN=128, BK=25, 256 threads, 8x8 micro-tile.
// Accumulators packed along N (f32x2): b operands load directly as 64-bit
// from smem (no packing movs); only the 8 a-splats need movs.
// Register-prefetch double buffering over the 20 K-tiles.
// Fused epilogue: writes g_h AND g_agg1 = b1 + h*dinv^2 (self-loop + bias).
__global__ void __launch_bounds__(256, 2) gemm1_kernel(const float* __restrict__ X,
                                                       const float* __restrict__ W,
                                                       const float* __restrict__ b1) {
    __shared__ float xs[25][132];   // transposed: xs[k][m], padded row (528B, 16B-aligned)
    __shared__ float ws[25][128];   // ws[k][n] (512B rows)
    const int m0  = blockIdx.x * 128;
    const int tid = threadIdx.x;
    const int tx  = tid & 15;       // 8 N-columns (4 packed pairs)
    const int ty  = tid >> 4;       // 8 M-rows

    unsigned long long acc[8][4];
    #pragma unroll
    for (int i = 0; i < 8; i++)
        #pragma unroll
        for (int j = 0; j < 4; j++) acc[i][j] = 0ULL;

    float px[13], pw[13];

    // preload tile 0 into registers
    #pragma unroll
    for (int it = 0; it < 13; it++) {
        int idx = tid + it * 256;
        if (idx < 3200) {
            int m = idx / 25, k = idx - m * 25;
            int gm = m0 + m;
            px[it] = (gm < N_NODES) ? X[(size_t)gm * D_IN + k] : 0.0f;
            int kw = idx >> 7, n = idx & 127;
            pw[it] = W[(size_t)kw * D_H + n];
        }
    }

    for (int t = 0; t < 20; t++) {
        __syncthreads();   // previous compute done before smem overwrite
        #pragma unroll
        for (int it = 0; it < 13; it++) {
            int idx = tid + it * 256;
            if (idx < 3200) {
                int m = idx / 25, k = idx - m * 25;
                xs[k][m] = px[it];
                int kw = idx >> 7, n = idx & 127;
                ws[kw][n] = pw[it];
            }
        }
        __syncthreads();

        if (t < 19) {
            int k0 = (t + 1) * 25;
            #pragma unroll
            for (int it = 0; it < 13; it++) {
                int idx = tid + it * 256;
                if (idx < 3200) {
                    int m = idx / 25, k = idx - m * 25;
                    int gm = m0 + m;
                    px[it] = (gm < N_NODES) ? X[(size_t)gm * D_IN + k0 + k] : 0.0f;
                    int kw = idx >> 7, n = idx & 127;
                    pw[it] = W[(size_t)(k0 + kw) * D_H + n];
                }
            }
        }

        #pragma unroll
        for (int kk = 0; kk < 25; kk++) {
            float4 a0 = *(const float4*)&xs[kk][ty * 8];
            float4 a1 = *(const float4*)&xs[kk][ty * 8 + 4];
            ulonglong2 b0 = *(const ulonglong2*)&ws[kk][tx * 8];
            ulonglong2 b1v = *(const ulonglong2*)&ws[kk][tx * 8 + 4];
            unsigned long long bb[4] = {b0.x, b0.y, b1v.x, b1v.y};
            float av[8] = {a0.x, a0.y, a0.z, a0.w, a1.x, a1.y, a1.z, a1.w};
            #pragma unroll
            for (int i = 0; i < 8; i++) {
                unsigned long long aa;
                asm("mov.b64 %0, {%1,%1};" : "=l"(aa) : "f"(av[i]));
                #pragma unroll
                for (int j = 0; j < 4; j++)
                    asm("fma.rn.f32x2 %0, %1, %2, %0;"
                        : "+l"(acc[i][j]) : "l"(aa), "l"(bb[j]));
            }
        }
    }

    // fused epilogue: g_h = h;  g_agg1 = b1 + h * dinv^2
    float4 bv0 = *(const float4*)&b1[tx * 8];
    float4 bv1 = *(const float4*)&b1[tx * 8 + 4];
    #pragma unroll
    for (int i = 0; i < 8; i++) {
        int gm = m0 + ty * 8 + i;
        if (gm < N_NODES) {
            float d  = g_dinv[gm];
            float d2 = d * d;
            float lo0, hi0, lo1, hi1;
            asm("mov.b64 {%0,%1}, %2;" : "=f"(lo0), "=f"(hi0) : "l"(acc[i][0]));
            asm("mov.b64 {%0,%1}, %2;" : "=f"(lo1), "=f"(hi1) : "l"(acc[i][1]));
            float4 o0 = make_float4(lo0, hi0, lo1, hi1);
            asm("mov.b64 {%0,%1}, %2;" : "=f"(lo0), "=f"(hi0) : "l"(acc[i][2]));
            asm("mov.b64 {%0,%1}, %2;" : "=f"(lo1), "=f"(hi1) : "l"(acc[i][3]));
            float4 o1 = make_float4(lo0, hi0, lo1, hi1);
            *(float4*)&g_h[(size_t)gm * D_H + tx * 8]     = o0;
            *(float4*)&g_h[(size_t)gm * D_H + tx * 8 + 4] = o1;
            float4 a0 = make_float4(fmaf(o0.x, d2, bv0.x), fmaf(o0.y, d2, bv0.y),
                                    fmaf(o0.z, d2, bv0.z), fmaf(o0.w, d2, bv0.w));
            float4 a1 = make_float4(fmaf(o1.x, d2, bv1.x), fmaf(o1.y, d2, bv1.y),
                                    fmaf(o1.z, d2, bv1.z), fmaf(o1.w, d2, bv1.w));
            *(float4*)&g_agg1[(size_t)gm * D_H + tx * 8]     = a0;
            *(float4*)&g_agg1[(size_t)gm * D_H + tx * 8 + 4] = a1;
        }
    }
}

// ---------------- scatter1: one warp per edge, 128 floats ----------------
__global__ void scatter1_kernel(const int* __restrict__ ei, int E) {
    int t = blockIdx.x * blockDim.x + threadIdx.x;
    int e = t >> 5;
    int l = t & 31;
    if (e >= E) return;
    int r = ei[e];
    int c = ei[E + e];
    float nrm = g_dinv[r] * g_dinv[c];
    float4 v = *(const float4*)&g_h[(size_t)r * D_H + l * 4];
    float* dst = &g_agg1[(size_t)c * D_H + l * 4];
    asm volatile("red.global.add.v4.f32 [%0], {%1,%2,%3,%4};"
                 :: "l"(dst), "f"(v.x * nrm), "f"(v.y * nrm),
                    "f"(v.z * nrm), "f"(v.w * nrm) : "memory");
}

// ---------------- GEMM2: g_h3 = relu(g_agg1)[100000,128] @ W2[128,64] -----
// Fused epilogue: g_h3 = h3;  g_agg2 = b2 + h3 * dinv^2
__global__ void __launch_bounds__(256) gemm2_kernel(const float* __restrict__ W,
                                                    const float* __restrict__ b2) {
    __shared__ float xs[32][132];   // transposed relu(A)
    __shared__ float ws[32][64];
    const int m0  = blockIdx.x * 128;
    const int tid = threadIdx.x;
    const int tx  = tid & 15;       // 4 cols each
    const int ty  = tid >> 4;       // 8 rows each

    float acc[8][4];
    #pragma unroll
    for (int i = 0; i < 8; i++)
        #pragma unroll
        for (int j = 0; j < 4; j++) acc[i][j] = 0.0f;

    for (int k0 = 0; k0 < D_H; k0 += 32) {
        #pragma unroll
        for (int it = 0; it < 16; it++) {
            int idx = tid + it * 256;         // 128*32 = 4096
            int m = idx >> 5, k = idx & 31;
            int gm = m0 + m;
            float v = (gm < N_NODES) ? g_agg1[(size_t)gm * D_H + k0 + k] : 0.0f;
            xs[k][m] = fmaxf(v, 0.0f);        // fused relu
        }
        #pragma unroll
        for (int it = 0; it < 8; it++) {
            int idx = tid + it * 256;         // 32*64 = 2048
            int k = idx >> 6, n = idx & 63;
            ws[k][n] = W[(size_t)(k0 + k) * D_O + n];
        }
        __syncthreads();

        #pragma unroll
        for (int kk = 0; kk < 32; kk++) {
            float4 a0 = *(const float4*)&xs[kk][ty * 8];
            float4 a1 = *(const float4*)&xs[kk][ty * 8 + 4];
            float4 b  = *(const float4*)&ws[kk][tx * 4];
            float av[8] = {a0.x, a0.y, a0.z, a0.w, a1.x, a1.y, a1.z, a1.w};
            float bv[4] = {b.x, b.y, b.z, b.w};
            #pragma unroll
            for (int i = 0; i < 8; i++)
                #pragma unroll
                for (int j = 0; j < 4; j++)
                    acc[i][j] = fmaf(av[i], bv[j], acc[i][j]);
        }
        __syncthreads();
    }

    float4 bv = *(const float4*)&b2[tx * 4];
    #pragma unroll
    for (int i = 0; i < 8; i++) {
        int gm = m0 + ty * 8 + i;
        if (gm < N_NODES) {
            float d  = g_dinv[gm];
            float d2 = d * d;
            float4 o = make_float4(acc[i][0], acc[i][1], acc[i][2], acc[i][3]);
            *(float4*)&g_h3[(size_t)gm * D_O + tx * 4] = o;
            float4 a = make_float4(fmaf(o.x, d2, bv.x), fmaf(o.y, d2, bv.y),
                                   fmaf(o.z, d2, bv.z), fmaf(o.w, d2, bv.w));
            *(float4*)&g_agg2[(size_t)gm * D_O + tx * 4] = a;
        }
    }
}

// ---------------- scatter2: 16 lanes per edge, 64 floats ----------------
__global__ void scatter2_kernel(const int* __restrict__ ei, int E) {
    int t = blockIdx.x * blockDim.x + threadIdx.x;
    int e = t >> 4;
    int l = t & 15;
    if (e >= E) return;
    int r = ei[e];
    int c = ei[E + e];
    float nrm = g_dinv[r] * g_dinv[c];
    float4 v = *(const float4*)&g_h3[(size_t)r * D_O + l * 4];
    float* dst = &g_agg2[(size_t)c * D_O + l * 4];
    asm volatile("red.global.add.v4.f32 [%0], {%1,%2,%3,%4};"
                 :: "l"(dst), "f"(v.x * nrm), "f"(v.y * nrm),
                    "f"(v.z * nrm), "f"(v.w * nrm) : "memory");
}

// ---------------- decode: scores[e] = dot(z[src], z[dst]) ----------------
__global__ void decode_kernel(const int* __restrict__ ei,
                              float* __restrict__ out, int E) {
    int t = blockIdx.x * blockDim.x + threadIdx.x;
    int e = t >> 4;
    int l = t & 15;
    if (e >= E) return;
    int a = ei[e];
    int b = ei[E + e];
    float4 va = *(const float4*)&g_agg2[(size_t)a * D_O + l * 4];
    float4 vb = *(const float4*)&g_agg2[(size_t)b * D_O + l * 4];
    float s = va.x * vb.x + va.y * vb.y + va.z * vb.z + va.w * vb.w;
    unsigned mask = __activemask();
    s += __shfl_xor_sync(mask, s, 1);
    s += __shfl_xor_sync(mask, s, 2);
    s += __shfl_xor_sync(mask, s, 4);
    s += __shfl_xor_sync(mask, s, 8);
    if (l == 0) out[e] = s;
}

// ---------------- launch ----------------
extern "C" void kernel_launch(void* const* d_in, const int* in_sizes, int n_in,
                              void* d_out, int out_size) {
    const float* x  = (const float*)d_in[0];
    const float* W1 = (const float*)d_in[1];
    const float* b1 = (const float*)d_in[2];
    const float* W2 = (const float*)d_in[3];
    const float* b2 = (const float*)d_in[4];
    const int*   ei = (const int*)d_in[5];
    const int E = in_sizes[5] / 2;

    deg_init_kernel<<<(N_NODES + 255) / 256, 256>>>();
    deg_count_kernel<<<(E + 255) / 256, 256>>>(ei + E, E);
    dinv_kernel<<<(N_NODES + 255) / 256, 256>>>();

    gemm1_kernel<<<(N_NODES + 127) / 128, 256>>>(x, W1, b1);
    scatter1_kernel<<<(int)(((long long)E * 32 + 255) / 256), 256>>>(ei, E);

    gemm2_kernel<<<(N_NODES + 127) / 128, 256>>>(W2, b2);
    scatter2_kernel<<<(int)(((long long)E * 16 + 255) / 256), 256>>>(ei, E);

    decode_kernel<<<(int)(((long long)E * 16 + 255) / 256), 256>>>(ei, (float*)d_out, E);
}

// round 3
// speedup vs baseline: 1.6438x; 1.4627x over previous
#include <cuda_runtime.h>
#include <cstdint>

#define N_NODES 100000
#define D_IN    500
#define D_H     128
#define D_O     64
#define E_MAX   3200000
#define NB1     ((N_NODES + 255) / 256)   // 391 scan blocks

// ---------------- scratch (device globals; no runtime allocation) ----------
__device__ int   g_cnt [N_NODES];                 // in-degree (excl self)
__device__ float g_dinv[N_NODES];
__device__ int   g_off [N_NODES];                 // CSR offsets (exclusive scan)
__device__ int   g_cur [N_NODES];                 // fill cursors
__device__ int   g_part[512];                     // scan partials
__device__ int   g_csr [E_MAX];                   // src node per in-edge, grouped by dst
__device__ float g_hs  [(size_t)N_NODES * D_H];   // (x@W1) * dinv
__device__ float g_acc1[(size_t)N_NODES * D_H];   // unscaled layer-1 aggregate
__device__ float g_hs2 [(size_t)N_NODES * D_O];   // (relu(agg1)@W2) * dinv
__device__ float g_z   [(size_t)N_NODES * D_O];   // final embeddings

// ---------------- degree / normalization / CSR build ----------------
__global__ void cnt_init_kernel() {
    int i = blockIdx.x * blockDim.x + threadIdx.x;
    if (i < N_NODES) g_cnt[i] = 0;
}

__global__ void deg_count_kernel(const int* __restrict__ col, int E) {
    int e = blockIdx.x * blockDim.x + threadIdx.x;
    if (e < E) atomicAdd(&g_cnt[col[e]], 1);
}

__global__ void dinv_kernel() {
    int i = blockIdx.x * blockDim.x + threadIdx.x;
    if (i < N_NODES) g_dinv[i] = rsqrtf((float)(g_cnt[i] + 1));
}

// exclusive scan, 3-phase
__global__ void scan1_kernel() {
    __shared__ int s[256];
    int tid = threadIdx.x;
    int i = blockIdx.x * 256 + tid;
    int v = (i < N_NODES) ? g_cnt[i] : 0;
    s[tid] = v;
    __syncthreads();
    #pragma unroll
    for (int d = 1; d < 256; d <<= 1) {
        int t = (tid >= d) ? s[tid - d] : 0;
        __syncthreads();
        s[tid] += t;
        __syncthreads();
    }
    if (i < N_NODES) g_off[i] = s[tid] - v;
    if (tid == 255) g_part[blockIdx.x] = s[255];
}

__global__ void scan2_kernel() {
    __shared__ int s[512];
    int tid = threadIdx.x;
    int v = (tid < NB1) ? g_part[tid] : 0;
    s[tid] = v;
    __syncthreads();
    #pragma unroll
    for (int d = 1; d < 512; d <<= 1) {
        int t = (tid >= d) ? s[tid - d] : 0;
        __syncthreads();
        s[tid] += t;
        __syncthreads();
    }
    if (tid < NB1) g_part[tid] = s[tid] - v;
}

__global__ void scan3_kernel() {
    int i = blockIdx.x * blockDim.x + threadIdx.x;
    if (i < N_NODES) {
        g_off[i] += g_part[blockIdx.x * 256 / 256 == 0 ? 0 : 0];  // placeholder avoided below
    }
}

// corrected: add block partial and zero cursors
__global__ void scan3b_kernel() {
    int i = blockIdx.x * blockDim.x + threadIdx.x;
    if (i < N_NODES) {
        g_off[i] += g_part[i >> 8];
        g_cur[i] = 0;
    }
}

__global__ void csr_fill_kernel(const int* __restrict__ ei, int E) {
    int e = blockIdx.x * blockDim.x + threadIdx.x;
    if (e >= E) return;
    int r = ei[e];
    int c = ei[E + e];
    int pos = g_off[c] + atomicAdd(&g_cur[c], 1);
    g_csr[pos] = r;
}

// ---------------- GEMM1: g_hs = (X[100000,500] @ W1[500,128]) * dinv -------
// BM=128, BN=128, BK=25, 256 threads, 8x8 micro-tile, f32x2 FMAs,
// register-prefetch double buffering.
__global__ void __launch_bounds__(256, 2) gemm1_kernel(const float* __restrict__ X,
                                                       const float* __restrict__ W) {
    __shared__ float xs[25][132];
    __shared__ float ws[25][128];
    const int m0  = blockIdx.x * 128;
    const int tid = threadIdx.x;
    const int tx  = tid & 15;
    const int ty  = tid >> 4;

    unsigned long long acc[8][4];
    #pragma unroll
    for (int i = 0; i < 8; i++)
        #pragma unroll
        for (int j = 0; j < 4; j++) acc[i][j] = 0ULL;

    float px[13], pw[13];
    #pragma unroll
    for (int it = 0; it < 13; it++) {
        int idx = tid + it * 256;
        if (idx < 3200) {
            int m = idx / 25, k = idx - m * 25;
            int gm = m0 + m;
            px[it] = (gm < N_NODES) ? X[(size_t)gm * D_IN + k] : 0.0f;
            int kw = idx >> 7, n = idx & 127;
            pw[it] = W[(size_t)kw * D_H + n];
        }
    }

    for (int t = 0; t < 20; t++) {
        __syncthreads();
        #pragma unroll
        for (int it = 0; it < 13; it++) {
            int idx = tid + it * 256;
            if (idx < 3200) {
                int m = idx / 25, k = idx - m * 25;
                xs[k][m] = px[it];
                int kw = idx >> 7, n = idx & 127;
                ws[kw][n] = pw[it];
            }
        }
        __syncthreads();

        if (t < 19) {
            int k0 = (t + 1) * 25;
            #pragma unroll
            for (int it = 0; it < 13; it++) {
                int idx = tid + it * 256;
                if (idx < 3200) {
                    int m = idx / 25, k = idx - m * 25;
                    int gm = m0 + m;
                    px[it] = (gm < N_NODES) ? X[(size_t)gm * D_IN + k0 + k] : 0.0f;
                    int kw = idx >> 7, n = idx & 127;
                    pw[it] = W[(size_t)(k0 + kw) * D_H + n];
                }
            }
        }

        #pragma unroll
        for (int kk = 0; kk < 25; kk++) {
            float4 a0 = *(const float4*)&xs[kk][ty * 8];
            float4 a1 = *(const float4*)&xs[kk][ty * 8 + 4];
            ulonglong2 b0 = *(const ulonglong2*)&ws[kk][tx * 8];
            ulonglong2 b1v = *(const ulonglong2*)&ws[kk][tx * 8 + 4];
            unsigned long long bb[4] = {b0.x, b0.y, b1v.x, b1v.y};
            float av[8] = {a0.x, a0.y, a0.z, a0.w, a1.x, a1.y, a1.z, a1.w};
            #pragma unroll
            for (int i = 0; i < 8; i++) {
                unsigned long long aa;
                asm("mov.b64 %0, {%1,%1};" : "=l"(aa) : "f"(av[i]));
                #pragma unroll
                for (int j = 0; j < 4; j++)
                    asm("fma.rn.f32x2 %0, %1, %2, %0;"
                        : "+l"(acc[i][j]) : "l"(aa), "l"(bb[j]));
            }
        }
    }

    // epilogue: g_hs = h * dinv
    #pragma unroll
    for (int i = 0; i < 8; i++) {
        int gm = m0 + ty * 8 + i;
        if (gm < N_NODES) {
            float d = g_dinv[gm];
            float lo0, hi0, lo1, hi1;
            asm("mov.b64 {%0,%1}, %2;" : "=f"(lo0), "=f"(hi0) : "l"(acc[i][0]));
            asm("mov.b64 {%0,%1}, %2;" : "=f"(lo1), "=f"(hi1) : "l"(acc[i][1]));
            float4 o0 = make_float4(lo0 * d, hi0 * d, lo1 * d, hi1 * d);
            asm("mov.b64 {%0,%1}, %2;" : "=f"(lo0), "=f"(hi0) : "l"(acc[i][2]));
            asm("mov.b64 {%0,%1}, %2;" : "=f"(lo1), "=f"(hi1) : "l"(acc[i][3]));
            float4 o1 = make_float4(lo0 * d, hi0 * d, lo1 * d, hi1 * d);
            *(float4*)&g_hs[(size_t)gm * D_H + tx * 8]     = o0;
            *(float4*)&g_hs[(size_t)gm * D_H + tx * 8 + 4] = o1;
        }
    }
}

// ---------------- agg1: CSR gather, warp per node, float4 lanes ------------
__global__ void __launch_bounds__(256) agg1_kernel() {
    int w = (blockIdx.x * blockDim.x + threadIdx.x) >> 5;
    int lane = threadIdx.x & 31;
    if (w >= N_NODES) return;
    int start = g_off[w];
    int cnt   = g_cnt[w];
    const float* base = &g_hs[(size_t)lane * 4];
    float4 acc = *(const float4*)&g_hs[(size_t)w * D_H + lane * 4];  // self-loop

    for (int b = 0; b < cnt; b += 32) {
        int n = min(32, cnt - b);
        int src = (lane < n) ? g_csr[start + b + lane] : 0;
        int j = 0;
        for (; j + 4 <= n; j += 4) {
            int s0 = __shfl_sync(0xffffffffu, src, j);
            int s1 = __shfl_sync(0xffffffffu, src, j + 1);
            int s2 = __shfl_sync(0xffffffffu, src, j + 2);
            int s3 = __shfl_sync(0xffffffffu, src, j + 3);
            float4 v0 = *(const float4*)(base + (size_t)s0 * D_H);
            float4 v1 = *(const float4*)(base + (size_t)s1 * D_H);
            float4 v2 = *(const float4*)(base + (size_t)s2 * D_H);
            float4 v3 = *(const float4*)(base + (size_t)s3 * D_H);
            acc.x += (v0.x + v1.x) + (v2.x + v3.x);
            acc.y += (v0.y + v1.y) + (v2.y + v3.y);
            acc.z += (v0.z + v1.z) + (v2.z + v3.z);
            acc.w += (v0.w + v1.w) + (v2.w + v3.w);
        }
        for (; j < n; j++) {
            int s = __shfl_sync(0xffffffffu, src, j);
            float4 v = *(const float4*)(base + (size_t)s * D_H);
            acc.x += v.x; acc.y += v.y; acc.z += v.z; acc.w += v.w;
        }
    }
    *(float4*)&g_acc1[(size_t)w * D_H + lane * 4] = acc;
}

// ---------------- GEMM2: g_hs2 = (relu(b1 + dinv*acc1) @ W2) * dinv --------
__global__ void __launch_bounds__(256) gemm2_kernel(const float* __restrict__ W,
                                                    const float* __restrict__ b1) {
    __shared__ float xs[32][132];
    __shared__ float ws[32][64];
    const int m0  = blockIdx.x * 128;
    const int tid = threadIdx.x;
    const int tx  = tid & 15;
    const int ty  = tid >> 4;

    float acc[8][4];
    #pragma unroll
    for (int i = 0; i < 8; i++)
        #pragma unroll
        for (int j = 0; j < 4; j++) acc[i][j] = 0.0f;

    for (int k0 = 0; k0 < D_H; k0 += 32) {
        #pragma unroll
        for (int it = 0; it < 16; it++) {
            int idx = tid + it * 256;
            int m = idx >> 5, k = idx & 31;
            int gm = m0 + m;
            float v = 0.0f;
            if (gm < N_NODES) {
                float d = g_dinv[gm];
                v = fmaf(g_acc1[(size_t)gm * D_H + k0 + k], d, b1[k0 + k]);
            }
            xs[k][m] = fmaxf(v, 0.0f);   // fused bias+scale+relu
        }
        #pragma unroll
        for (int it = 0; it < 8; it++) {
            int idx = tid + it * 256;
            int k = idx >> 6, n = idx & 63;
            ws[k][n] = W[(size_t)(k0 + k) * D_O + n];
        }
        __syncthreads();

        #pragma unroll
        for (int kk = 0; kk < 32; kk++) {
            float4 a0 = *(const float4*)&xs[kk][ty * 8];
            float4 a1 = *(const float4*)&xs[kk][ty * 8 + 4];
            float4 b  = *(const float4*)&ws[kk][tx * 4];
            float av[8] = {a0.x, a0.y, a0.z, a0.w, a1.x, a1.y, a1.z, a1.w};
            float bv[4] = {b.x, b.y, b.z, b.w};
            #pragma unroll
            for (int i = 0; i < 8; i++)
                #pragma unroll
                for (int j = 0; j < 4; j++)
                    acc[i][j] = fmaf(av[i], bv[j], acc[i][j]);
        }
        __syncthreads();
    }

    #pragma unroll
    for (int i = 0; i < 8; i++) {
        int gm = m0 + ty * 8 + i;
        if (gm < N_NODES) {
            float d = g_dinv[gm];
            float4 o = make_float4(acc[i][0] * d, acc[i][1] * d,
                                   acc[i][2] * d, acc[i][3] * d);
            *(float4*)&g_hs2[(size_t)gm * D_O + tx * 4] = o;
        }
    }
}

// ---------------- agg2: CSR gather, warp per node, float2 lanes ------------
__global__ void __launch_bounds__(256) agg2_kernel(const float* __restrict__ b2) {
    int w = (blockIdx.x * blockDim.x + threadIdx.x) >> 5;
    int lane = threadIdx.x & 31;
    if (w >= N_NODES) return;
    int start = g_off[w];
    int cnt   = g_cnt[w];
    const float* base = &g_hs2[(size_t)lane * 2];
    float2 acc = *(const float2*)&g_hs2[(size_t)w * D_O + lane * 2];  // self-loop

    for (int b = 0; b < cnt; b += 32) {
        int n = min(32, cnt - b);
        int src = (lane < n) ? g_csr[start + b + lane] : 0;
        int j = 0;
        for (; j + 4 <= n; j += 4) {
            int s0 = __shfl_sync(0xffffffffu, src, j);
            int s1 = __shfl_sync(0xffffffffu, src, j + 1);
            int s2 = __shfl_sync(0xffffffffu, src, j + 2);
            int s3 = __shfl_sync(0xffffffffu, src, j + 3);
            float2 v0 = *(const float2*)(base + (size_t)s0 * D_O);
            float2 v1 = *(const float2*)(base + (size_t)s1 * D_O);
            float2 v2 = *(const float2*)(base + (size_t)s2 * D_O);
            float2 v3 = *(const float2*)(base + (size_t)s3 * D_O);
            acc.x += (v0.x + v1.x) + (v2.x + v3.x);
            acc.y += (v0.y + v1.y) + (v2.y + v3.y);
        }
        for (; j < n; j++) {
            int s = __shfl_sync(0xffffffffu, src, j);
            float2 v = *(const float2*)(base + (size_t)s * D_O);
            acc.x += v.x; acc.y += v.y;
        }
    }
    float d = g_dinv[w];
    float2 z = make_float2(fmaf(acc.x, d, b2[lane * 2]),
                           fmaf(acc.y, d, b2[lane * 2 + 1]));
    *(float2*)&g_z[(size_t)w * D_O + lane * 2] = z;
}

// ---------------- decode: scores[e] = dot(z[src], z[dst]) ----------------
__global__ void decode_kernel(const int* __restrict__ ei,
                              float* __restrict__ out, int E) {
    int t = blockIdx.x * blockDim.x + threadIdx.x;
    int e = t >> 4;
    int l = t & 15;
    if (e >= E) return;
    int a = ei[e];
    int b = ei[E + e];
    float4 va = *(const float4*)&g_z[(size_t)a * D_O + l * 4];
    float4 vb = *(const float4*)&g_z[(size_t)b * D_O + l * 4];
    float s = va.x * vb.x + va.y * vb.y + va.z * vb.z + va.w * vb.w;
    unsigned mask = __activemask();
    s += __shfl_xor_sync(mask, s, 1);
    s += __shfl_xor_sync(mask, s, 2);
    s += __shfl_xor_sync(mask, s, 4);
    s += __shfl_xor_sync(mask, s, 8);
    if (l == 0) out[e] = s;
}

// ---------------- launch ----------------
extern "C" void kernel_launch(void* const* d_in, const int* in_sizes, int n_in,
                              void* d_out, int out_size) {
    const float* x  = (const float*)d_in[0];
    const float* W1 = (const float*)d_in[1];
    const float* b1 = (const float*)d_in[2];
    const float* W2 = (const float*)d_in[3];
    const float* b2 = (const float*)d_in[4];
    const int*   ei = (const int*)d_in[5];
    const int E = in_sizes[5] / 2;

    cnt_init_kernel<<<NB1, 256>>>();
    deg_count_kernel<<<(E + 255) / 256, 256>>>(ei + E, E);
    dinv_kernel<<<NB1, 256>>>();
    scan1_kernel<<<NB1, 256>>>();
    scan2_kernel<<<1, 512>>>();
    scan3b_kernel<<<NB1, 256>>>();
    csr_fill_kernel<<<(E + 255) / 256, 256>>>(ei, E);

    gemm1_kernel<<<(N_NODES + 127) / 128, 256>>>(x, W1);
    agg1_kernel<<<(N_NODES * 32 + 255) / 256, 256>>>();

    gemm2_kernel<<<(N_NODES + 127) / 128, 256>>>(W2, b1);
    agg2_kernel<<<(N_NODES * 32 + 255) / 256, 256>>>(b2);

    decode_kernel<<<(int)(((long long)E * 16 + 255) / 256), 256>>>(ei, (float*)d_out, E);
}

// round 6
// speedup vs baseline: 2.0853x; 1.2686x over previous
#include <cuda_runtime.h>
#include <cuda_bf16.h>
#include <cstdint>

#define N_NODES 100000
#define D_IN    500
#define D_H     128
#define D_O     64
#define E_MAX   3200000
#define NB1     ((N_NODES + 255) / 256)

// ---------------- scratch ----------------
__device__ int   g_cnt [N_NODES];
__device__ float g_dinv[N_NODES];
__device__ int   g_off [N_NODES];
__device__ int   g_cur [N_NODES];
__device__ int   g_part[512];
__device__ int   g_csr [E_MAX];
// W1^T bf16 hi/lo pre-packed in mma.m16n8k16 B-fragment order:
// idx = kstep*1024 + npair*128 + lane*4 + (ntile&1)*2 + reg  (kstep<32, npair<8)
__device__ __align__(16) uint32_t g_bhi[32 * 1024];
__device__ __align__(16) uint32_t g_blo[32 * 1024];
__device__ float g_hs  [(size_t)N_NODES * D_H];
__device__ float g_acc1[(size_t)N_NODES * D_H];
__device__ float g_hs2 [(size_t)N_NODES * D_O];
__device__ float g_z   [(size_t)N_NODES * D_O];

__device__ __forceinline__ uint32_t smem_u32(const void* p) {
    uint32_t a;
    asm("{ .reg .u64 t; cvta.to.shared.u64 t, %1; cvt.u32.u64 %0, t; }"
        : "=r"(a) : "l"(p));
    return a;
}

// ---------------- degree / CSR ----------------
__global__ void cnt_init_kernel() {
    int i = blockIdx.x * blockDim.x + threadIdx.x;
    if (i < N_NODES) g_cnt[i] = 0;
}
__global__ void deg_count_kernel(const int* __restrict__ col, int E) {
    int e = blockIdx.x * blockDim.x + threadIdx.x;
    if (e < E) atomicAdd(&g_cnt[col[e]], 1);
}
__global__ void dinv_kernel() {
    int i = blockIdx.x * blockDim.x + threadIdx.x;
    if (i < N_NODES) g_dinv[i] = rsqrtf((float)(g_cnt[i] + 1));
}
__global__ void scan1_kernel() {
    __shared__ int s[256];
    int tid = threadIdx.x;
    int i = blockIdx.x * 256 + tid;
    int v = (i < N_NODES) ? g_cnt[i] : 0;
    s[tid] = v;
    __syncthreads();
    #pragma unroll
    for (int d = 1; d < 256; d <<= 1) {
        int t = (tid >= d) ? s[tid - d] : 0;
        __syncthreads();
        s[tid] += t;
        __syncthreads();
    }
    if (i < N_NODES) g_off[i] = s[tid] - v;
    if (tid == 255) g_part[blockIdx.x] = s[255];
}
__global__ void scan2_kernel() {
    __shared__ int s[512];
    int tid = threadIdx.x;
    int v = (tid < NB1) ? g_part[tid] : 0;
    s[tid] = v;
    __syncthreads();
    #pragma unroll
    for (int d = 1; d < 512; d <<= 1) {
        int t = (tid >= d) ? s[tid - d] : 0;
        __syncthreads();
        s[tid] += t;
        __syncthreads();
    }
    if (tid < NB1) g_part[tid] = s[tid] - v;
}
__global__ void scan3b_kernel() {
    int i = blockIdx.x * blockDim.x + threadIdx.x;
    if (i < N_NODES) {
        g_off[i] += g_part[i >> 8];
        g_cur[i] = 0;
    }
}
__global__ void csr_fill_kernel(const int* __restrict__ ei, int E) {
    int e = blockIdx.x * blockDim.x + threadIdx.x;
    if (e >= E) return;
    int r = ei[e];
    int c = ei[E + e];
    int pos = g_off[c] + atomicAdd(&g_cur[c], 1);
    g_csr[pos] = r;
}

// ---------------- W1 split into mma B fragments ----------------
// B = W1^T: fragment reg for (kstep, ntile, lane, reg):
//   n = ntile*8 + lane/4 ;  k = kstep*16 + reg*8 + (lane%4)*2
//   packed bf16x2 = ( W[k][n], W[k+1][n] )
__global__ void w1split_kernel(const float* __restrict__ W1) {
    int i = blockIdx.x * blockDim.x + threadIdx.x;   // 32*16*32*2 = 32768
    if (i >= 32768) return;
    int reg   = i & 1;
    int lane  = (i >> 1) & 31;
    int ntile = (i >> 6) & 15;
    int kstep = i >> 10;
    int n = ntile * 8 + (lane >> 2);
    int k = kstep * 16 + reg * 8 + (lane & 3) * 2;

    float w0 = (k     < D_IN) ? W1[(size_t)k * D_H + n]       : 0.0f;
    float w1 = (k + 1 < D_IN) ? W1[(size_t)(k + 1) * D_H + n] : 0.0f;
    __nv_bfloat16 h0 = __float2bfloat16(w0);
    __nv_bfloat16 h1 = __float2bfloat16(w1);
    __nv_bfloat16 l0 = __float2bfloat16(w0 - __bfloat162float(h0));
    __nv_bfloat16 l1 = __float2bfloat16(w1 - __bfloat162float(h1));
    __nv_bfloat162 hp = {h0, h1}, lp = {l0, l1};

    int idx = kstep * 1024 + (ntile >> 1) * 128 + lane * 4 + (ntile & 1) * 2 + reg;
    g_bhi[idx] = *(uint32_t*)&hp;
    g_blo[idx] = *(uint32_t*)&lp;
}

// ---------------- GEMM1 (mma.sync bf16 hi/lo split) ----------------
// g_hs[m][n] = dinv[m] * sum_k X[m][k] * W1[k][n]
__global__ void __launch_bounds__(256) gemm1_mma_kernel(const float* __restrict__ X) {
    __shared__ __align__(16) uint8_t Ahi[128 * 128];  // 128 rows x 64 bf16 (swizzled)
    __shared__ __align__(16) uint8_t Alo[128 * 128];

    const int tid  = threadIdx.x;
    const int wid  = tid >> 5;
    const int lane = tid & 31;
    const int m0   = blockIdx.x * 128;
    const int warp_m = (wid >> 1) * 32;    // 4 M-warps
    const int warp_n = (wid & 1) * 64;     // 2 N-warps

    const uint32_t ahi_base = smem_u32(Ahi);
    const uint32_t alo_base = smem_u32(Alo);

    // A-load assignment: 2 threads per row, 32 fp32 (8 float4) each
    const int arow  = tid >> 1;
    const int ahalf = tid & 1;
    const int gm    = m0 + arow;
    const float* xrow = X + (size_t)gm * D_IN;
    const bool rok = (gm < N_NODES);

    float acc[2][8][4];
    #pragma unroll
    for (int mt = 0; mt < 2; mt++)
        #pragma unroll
        for (int nt = 0; nt < 8; nt++)
            #pragma unroll
            for (int r = 0; r < 4; r++) acc[mt][nt][r] = 0.0f;

    for (int chunk = 0; chunk < 8; chunk++) {
        if (chunk > 0) __syncthreads();
        // load + split X chunk: rows 128 x k [chunk*64, +64)
        #pragma unroll
        for (int q = 0; q < 8; q++) {
            int kl = ahalf * 32 + q * 4;
            int kg = chunk * 64 + kl;
            float4 v = make_float4(0.f, 0.f, 0.f, 0.f);
            if (rok && kg < D_IN) v = *(const float4*)(xrow + kg);
            __nv_bfloat16 h0 = __float2bfloat16(v.x);
            __nv_bfloat16 h1 = __float2bfloat16(v.y);
            __nv_bfloat16 h2 = __float2bfloat16(v.z);
            __nv_bfloat16 h3 = __float2bfloat16(v.w);
            __nv_bfloat16 l0 = __float2bfloat16(v.x - __bfloat162float(h0));
            __nv_bfloat16 l1 = __float2bfloat16(v.y - __bfloat162float(h1));
            __nv_bfloat16 l2 = __float2bfloat16(v.z - __bfloat162float(h2));
            __nv_bfloat16 l3 = __float2bfloat16(v.w - __bfloat162float(h3));
            int ch  = kl >> 3;
            int sub = (kl & 7) ? 8 : 0;
            uint32_t off = arow * 128 + ((ch ^ (arow & 7)) << 4) + sub;
            __nv_bfloat162 hp0 = {h0, h1}, hp1 = {h2, h3};
            __nv_bfloat162 lp0 = {l0, l1}, lp1 = {l2, l3};
            uint2 hv = { *(uint32_t*)&hp0, *(uint32_t*)&hp1 };
            uint2 lv = { *(uint32_t*)&lp0, *(uint32_t*)&lp1 };
            *(uint2*)(Ahi + off) = hv;
            *(uint2*)(Alo + off) = lv;
        }
        __syncthreads();

        #pragma unroll
        for (int kstep = 0; kstep < 4; kstep++) {
            int kg = chunk * 4 + kstep;
            uint32_t ah[2][4], al[2][4];
            #pragma unroll
            for (int mt = 0; mt < 2; mt++) {
                int mrow = warp_m + mt * 16 + (lane & 7) + ((lane & 8) ? 8 : 0);
                int ch   = kstep * 2 + (lane >> 4);
                uint32_t off = mrow * 128 + ((ch ^ (mrow & 7)) << 4);
                asm volatile("ldmatrix.sync.aligned.m8n8.x4.shared.b16 {%0,%1,%2,%3}, [%4];"
                             : "=r"(ah[mt][0]), "=r"(ah[mt][1]), "=r"(ah[mt][2]), "=r"(ah[mt][3])
                             : "r"(ahi_base + off));
                asm volatile("ldmatrix.sync.aligned.m8n8.x4.shared.b16 {%0,%1,%2,%3}, [%4];"
                             : "=r"(al[mt][0]), "=r"(al[mt][1]), "=r"(al[mt][2]), "=r"(al[mt][3])
                             : "r"(alo_base + off));
            }
            uint4 bh[4], bl[4];
            #pragma unroll
            for (int p = 0; p < 4; p++) {
                int npair = (warp_n >> 4) + p;
                int idx = kg * 1024 + npair * 128 + lane * 4;
                bh[p] = *(const uint4*)(g_bhi + idx);
                bl[p] = *(const uint4*)(g_blo + idx);
            }
            #pragma unroll
            for (int mt = 0; mt < 2; mt++) {
                #pragma unroll
                for (int nt = 0; nt < 8; nt++) {
                    int p = nt >> 1;
                    uint32_t bh0 = (nt & 1) ? bh[p].z : bh[p].x;
                    uint32_t bh1 = (nt & 1) ? bh[p].w : bh[p].y;
                    uint32_t bl0 = (nt & 1) ? bl[p].z : bl[p].x;
                    uint32_t bl1 = (nt & 1) ? bl[p].w : bl[p].y;
                    float* c = acc[mt][nt];
                    asm volatile("mma.sync.aligned.m16n8k16.row.col.f32.bf16.bf16.f32 "
                        "{%0,%1,%2,%3}, {%4,%5,%6,%7}, {%8,%9}, {%0,%1,%2,%3};"
                        : "+f"(c[0]), "+f"(c[1]), "+f"(c[2]), "+f"(c[3])
                        : "r"(ah[mt][0]), "r"(ah[mt][1]), "r"(ah[mt][2]), "r"(ah[mt][3]),
                          "r"(bh0), "r"(bh1));
                    asm volatile("mma.sync.aligned.m16n8k16.row.col.f32.bf16.bf16.f32 "
                        "{%0,%1,%2,%3}, {%4,%5,%6,%7}, {%8,%9}, {%0,%1,%2,%3};"
                        : "+f"(c[0]), "+f"(c[1]), "+f"(c[2]), "+f"(c[3])
                        : "r"(ah[mt][0]), "r"(ah[mt][1]), "r"(ah[mt][2]), "r"(ah[mt][3]),
                          "r"(bl0), "r"(bl1));
                    asm volatile("mma.sync.aligned.m16n8k16.row.col.f32.bf16.bf16.f32 "
                        "{%0,%1,%2,%3}, {%4,%5,%6,%7}, {%8,%9}, {%0,%1,%2,%3};"
                        : "+f"(c[0]), "+f"(c[1]), "+f"(c[2]), "+f"(c[3])
                        : "r"(al[mt][0]), "r"(al[mt][1]), "r"(al[mt][2]), "r"(al[mt][3]),
                          "r"(bh0), "r"(bh1));
                }
            }
        }
    }

    // epilogue: regs {0,1}=row, {2,3}=row+8, cols (lane%4)*2
    #pragma unroll
    for (int mt = 0; mt < 2; mt++) {
        int r0 = m0 + warp_m + mt * 16 + (lane >> 2);
        int r1 = r0 + 8;
        float d0 = (r0 < N_NODES) ? g_dinv[r0] : 0.0f;
        float d1 = (r1 < N_NODES) ? g_dinv[r1] : 0.0f;
        #pragma unroll
        for (int nt = 0; nt < 8; nt++) {
            int cc = warp_n + nt * 8 + (lane & 3) * 2;
            if (r0 < N_NODES) {
                float2 o = make_float2(acc[mt][nt][0] * d0, acc[mt][nt][1] * d0);
                *(float2*)&g_hs[(size_t)r0 * D_H + cc] = o;
            }
            if (r1 < N_NODES) {
                float2 o = make_float2(acc[mt][nt][2] * d1, acc[mt][nt][3] * d1);
                *(float2*)&g_hs[(size_t)r1 * D_H + cc] = o;
            }
        }
    }
}

// ---------------- agg1: CSR gather, warp per node, float4 lanes ------------
__global__ void __launch_bounds__(256) agg1_kernel() {
    int w = (blockIdx.x * blockDim.x + threadIdx.x) >> 5;
    int lane = threadIdx.x & 31;
    if (w >= N_NODES) return;
    int start = g_off[w];
    int cnt   = g_cnt[w];
    const float* base = &g_hs[(size_t)lane * 4];
    float4 acc = *(const float4*)&g_hs[(size_t)w * D_H + lane * 4];

    for (int b = 0; b < cnt; b += 32) {
        int n = min(32, cnt - b);
        int src = (lane < n) ? g_csr[start + b + lane] : 0;
        int j = 0;
        for (; j + 4 <= n; j += 4) {
            int s0 = __shfl_sync(0xffffffffu, src, j);
            int s1 = __shfl_sync(0xffffffffu, src, j + 1);
            int s2 = __shfl_sync(0xffffffffu, src, j + 2);
            int s3 = __shfl_sync(0xffffffffu, src, j + 3);
            float4 v0 = *(const float4*)(base + (size_t)s0 * D_H);
            float4 v1 = *(const float4*)(base + (size_t)s1 * D_H);
            float4 v2 = *(const float4*)(base + (size_t)s2 * D_H);
            float4 v3 = *(const float4*)(base + (size_t)s3 * D_H);
            acc.x += (v0.x + v1.x) + (v2.x + v3.x);
            acc.y += (v0.y + v1.y) + (v2.y + v3.y);
            acc.z += (v0.z + v1.z) + (v2.z + v3.z);
            acc.w += (v0.w + v1.w) + (v2.w + v3.w);
        }
        for (; j < n; j++) {
            int s = __shfl_sync(0xffffffffu, src, j);
            float4 v = *(const float4*)(base + (size_t)s * D_H);
            acc.x += v.x; acc.y += v.y; acc.z += v.z; acc.w += v.w;
        }
    }
    *(float4*)&g_acc1[(size_t)w * D_H + lane * 4] = acc;
}

// ---------------- GEMM2: g_hs2 = (relu(b1 + dinv*acc1) @ W2) * dinv --------
__global__ void __launch_bounds__(256) gemm2_kernel(const float* __restrict__ W,
                                                    const float* __restrict__ b1) {
    __shared__ float xs[32][132];
    __shared__ float ws[32][64];
    const int m0  = blockIdx.x * 128;
    const int tid = threadIdx.x;
    const int tx  = tid & 15;
    const int ty  = tid >> 4;

    float acc[8][4];
    #pragma unroll
    for (int i = 0; i < 8; i++)
        #pragma unroll
        for (int j = 0; j < 4; j++) acc[i][j] = 0.0f;

    for (int k0 = 0; k0 < D_H; k0 += 32) {
        #pragma unroll
        for (int it = 0; it < 16; it++) {
            int idx = tid + it * 256;
            int m = idx >> 5, k = idx & 31;
            int gm = m0 + m;
            float v = 0.0f;
            if (gm < N_NODES) {
                float d = g_dinv[gm];
                v = fmaf(g_acc1[(size_t)gm * D_H + k0 + k], d, b1[k0 + k]);
            }
            xs[k][m] = fmaxf(v, 0.0f);
        }
        #pragma unroll
        for (int it = 0; it < 8; it++) {
            int idx = tid + it * 256;
            int k = idx >> 6, n = idx & 63;
            ws[k][n] = W[(size_t)(k0 + k) * D_O + n];
        }
        __syncthreads();

        #pragma unroll
        for (int kk = 0; kk < 32; kk++) {
            float4 a0 = *(const float4*)&xs[kk][ty * 8];
            float4 a1 = *(const float4*)&xs[kk][ty * 8 + 4];
            float4 b  = *(const float4*)&ws[kk][tx * 4];
            float av[8] = {a0.x, a0.y, a0.z, a0.w, a1.x, a1.y, a1.z, a1.w};
            float bv[4] = {b.x, b.y, b.z, b.w};
            #pragma unroll
            for (int i = 0; i < 8; i++)
                #pragma unroll
                for (int j = 0; j < 4; j++)
                    acc[i][j] = fmaf(av[i], bv[j], acc[i][j]);
        }
        __syncthreads();
    }

    #pragma unroll
    for (int i = 0; i < 8; i++) {
        int gm = m0 + ty * 8 + i;
        if (gm < N_NODES) {
            float d = g_dinv[gm];
            float4 o = make_float4(acc[i][0] * d, acc[i][1] * d,
                                   acc[i][2] * d, acc[i][3] * d);
            *(float4*)&g_hs2[(size_t)gm * D_O + tx * 4] = o;
        }
    }
}

// ---------------- agg2: CSR gather, warp per node, float2 lanes ------------
__global__ void __launch_bounds__(256) agg2_kernel(const float* __restrict__ b2) {
    int w = (blockIdx.x * blockDim.x + threadIdx.x) >> 5;
    int lane = threadIdx.x & 31;
    if (w >= N_NODES) return;
    int start = g_off[w];
    int cnt   = g_cnt[w];
    const float* base = &g_hs2[(size_t)lane * 2];
    float2 acc = *(const float2*)&g_hs2[(size_t)w * D_O + lane * 2];

    for (int b = 0; b < cnt; b += 32) {
        int n = min(32, cnt - b);
        int src = (lane < n) ? g_csr[start + b + lane] : 0;
        int j = 0;
        for (; j + 4 <= n; j += 4) {
            int s0 = __shfl_sync(0xffffffffu, src, j);
            int s1 = __shfl_sync(0xffffffffu, src, j + 1);
            int s2 = __shfl_sync(0xffffffffu, src, j + 2);
            int s3 = __shfl_sync(0xffffffffu, src, j + 3);
            float2 v0 = *(const float2*)(base + (size_t)s0 * D_O);
            float2 v1 = *(const float2*)(base + (size_t)s1 * D_O);
            float2 v2 = *(const float2*)(base + (size_t)s2 * D_O);
            float2 v3 = *(const float2*)(base + (size_t)s3 * D_O);
            acc.x += (v0.x + v1.x) + (v2.x + v3.x);
            acc.y += (v0.y + v1.y) + (v2.y + v3.y);
        }
        for (; j < n; j++) {
            int s = __shfl_sync(0xffffffffu, src, j);
            float2 v = *(const float2*)(base + (size_t)s * D_O);
            acc.x += v.x; acc.y += v.y;
        }
    }
    float d = g_dinv[w];
    float2 z = make_float2(fmaf(acc.x, d, b2[lane * 2]),
                           fmaf(acc.y, d, b2[lane * 2 + 1]));
    *(float2*)&g_z[(size_t)w * D_O + lane * 2] = z;
}

// ---------------- decode ----------------
__global__ void decode_kernel(const int* __restrict__ ei,
                              float* __restrict__ out, int E) {
    int t = blockIdx.x * blockDim.x + threadIdx.x;
    int e = t >> 4;
    int l = t & 15;
    if (e >= E) return;
    int a = ei[e];
    int b = ei[E + e];
    float4 va = *(const float4*)&g_z[(size_t)a * D_O + l * 4];
    float4 vb = *(const float4*)&g_z[(size_t)b * D_O + l * 4];
    float s = va.x * vb.x + va.y * vb.y + va.z * vb.z + va.w * vb.w;
    unsigned mask = __activemask();
    s += __shfl_xor_sync(mask, s, 1);
    s += __shfl_xor_sync(mask, s, 2);
    s += __shfl_xor_sync(mask, s, 4);
    s += __shfl_xor_sync(mask, s, 8);
    if (l == 0) out[e] = s;
}

// ---------------- launch ----------------
extern "C" void kernel_launch(void* const* d_in, const int* in_sizes, int n_in,
                              void* d_out, int out_size) {
    const float* x  = (const float*)d_in[0];
    const float* W1 = (const float*)d_in[1];
    const float* b1 = (const float*)d_in[2];
    const float* W2 = (const float*)d_in[3];
    const float* b2 = (const float*)d_in[4];
    const int*   ei = (const int*)d_in[5];
    const int E = in_sizes[5] / 2;

    cnt_init_kernel<<<NB1, 256>>>();
    deg_count_kernel<<<(E + 255) / 256, 256>>>(ei + E, E);
    dinv_kernel<<<NB1, 256>>>();
    scan1_kernel<<<NB1, 256>>>();
    scan2_kernel<<<1, 512>>>();
    scan3b_kernel<<<NB1, 256>>>();
    csr_fill_kernel<<<(E + 255) / 256, 256>>>(ei, E);

    w1split_kernel<<<128, 256>>>(W1);
    gemm1_mma_kernel<<<(N_NODES + 127) / 128, 256>>>(x);
    agg1_kernel<<<(N_NODES * 32 + 255) / 256, 256>>>();

    gemm2_kernel<<<(N_NODES + 127) / 128, 256>>>(W2, b1);
    agg2_kernel<<<(N_NODES * 32 + 255) / 256, 256>>>(b2);

    decode_kernel<<<(int)(((long long)E * 16 + 255) / 256), 256>>>(ei, (float*)d_out, E);
}

// round 7
// speedup vs baseline: 2.3170x; 1.1111x over previous
#include <cuda_runtime.h>
#include <cuda_bf16.h>
#include <cstdint>

#define N_NODES 100000
#define D_IN    500
#define D_H     128
#define D_O     64
#define E_MAX   3200000
#define NB1     ((N_NODES + 255) / 256)

// ---------------- scratch ----------------
__device__ int   g_cnt [N_NODES];
__device__ float g_dinv[N_NODES];
__device__ int   g_off [N_NODES];
__device__ int   g_cur [N_NODES];
__device__ int   g_part[512];
__device__ int   g_csr [E_MAX];   // src node per in-edge, grouped by dst
__device__ int   g_eid [E_MAX];   // original edge id per CSR slot
// W1^T bf16 hi/lo pre-packed in mma.m16n8k16 B-fragment order:
// idx = kstep*1024 + npair*128 + lane*4 + (ntile&1)*2 + reg  (kstep<32, npair<8)
__device__ __align__(16) uint32_t g_bhi[32 * 1024];
__device__ __align__(16) uint32_t g_blo[32 * 1024];
__device__ float g_hs  [(size_t)N_NODES * D_H];
__device__ float g_acc1[(size_t)N_NODES * D_H];
__device__ float g_hs2 [(size_t)N_NODES * D_O];
__device__ float g_z   [(size_t)N_NODES * D_O];

__device__ __forceinline__ uint32_t smem_u32(const void* p) {
    uint32_t a;
    asm("{ .reg .u64 t; cvta.to.shared.u64 t, %1; cvt.u32.u64 %0, t; }"
        : "=r"(a) : "l"(p));
    return a;
}

// ---------------- degree / CSR ----------------
__global__ void cnt_init_kernel() {
    int i = blockIdx.x * blockDim.x + threadIdx.x;
    if (i < N_NODES) g_cnt[i] = 0;
}
__global__ void deg_count_kernel(const int* __restrict__ col, int E) {
    int e = blockIdx.x * blockDim.x + threadIdx.x;
    if (e < E) atomicAdd(&g_cnt[col[e]], 1);
}
__global__ void dinv_kernel() {
    int i = blockIdx.x * blockDim.x + threadIdx.x;
    if (i < N_NODES) g_dinv[i] = rsqrtf((float)(g_cnt[i] + 1));
}
__global__ void scan1_kernel() {
    __shared__ int s[256];
    int tid = threadIdx.x;
    int i = blockIdx.x * 256 + tid;
    int v = (i < N_NODES) ? g_cnt[i] : 0;
    s[tid] = v;
    __syncthreads();
    #pragma unroll
    for (int d = 1; d < 256; d <<= 1) {
        int t = (tid >= d) ? s[tid - d] : 0;
        __syncthreads();
        s[tid] += t;
        __syncthreads();
    }
    if (i < N_NODES) g_off[i] = s[tid] - v;
    if (tid == 255) g_part[blockIdx.x] = s[255];
}
__global__ void scan2_kernel() {
    __shared__ int s[512];
    int tid = threadIdx.x;
    int v = (tid < NB1) ? g_part[tid] : 0;
    s[tid] = v;
    __syncthreads();
    #pragma unroll
    for (int d = 1; d < 512; d <<= 1) {
        int t = (tid >= d) ? s[tid - d] : 0;
        __syncthreads();
        s[tid] += t;
        __syncthreads();
    }
    if (tid < NB1) g_part[tid] = s[tid] - v;
}
__global__ void scan3b_kernel() {
    int i = blockIdx.x * blockDim.x + threadIdx.x;
    if (i < N_NODES) {
        g_off[i] += g_part[i >> 8];
        g_cur[i] = 0;
    }
}
__global__ void csr_fill_kernel(const int* __restrict__ ei, int E) {
    int e = blockIdx.x * blockDim.x + threadIdx.x;
    if (e >= E) return;
    int r = ei[e];
    int c = ei[E + e];
    int pos = g_off[c] + atomicAdd(&g_cur[c], 1);
    g_csr[pos] = r;
    g_eid[pos] = e;
}

// ---------------- W1 split into mma B fragments ----------------
__global__ void w1split_kernel(const float* __restrict__ W1) {
    int i = blockIdx.x * blockDim.x + threadIdx.x;   // 32*16*32*2 = 32768
    if (i >= 32768) return;
    int reg   = i & 1;
    int lane  = (i >> 1) & 31;
    int ntile = (i >> 6) & 15;
    int kstep = i >> 10;
    int n = ntile * 8 + (lane >> 2);
    int k = kstep * 16 + reg * 8 + (lane & 3) * 2;

    float w0 = (k     < D_IN) ? W1[(size_t)k * D_H + n]       : 0.0f;
    float w1 = (k + 1 < D_IN) ? W1[(size_t)(k + 1) * D_H + n] : 0.0f;
    __nv_bfloat16 h0 = __float2bfloat16(w0);
    __nv_bfloat16 h1 = __float2bfloat16(w1);
    __nv_bfloat16 l0 = __float2bfloat16(w0 - __bfloat162float(h0));
    __nv_bfloat16 l1 = __float2bfloat16(w1 - __bfloat162float(h1));
    __nv_bfloat162 hp = {h0, h1}, lp = {l0, l1};

    int idx = kstep * 1024 + (ntile >> 1) * 128 + lane * 4 + (ntile & 1) * 2 + reg;
    g_bhi[idx] = *(uint32_t*)&hp;
    g_blo[idx] = *(uint32_t*)&lp;
}

// ---------------- GEMM1 (mma.sync bf16 hi/lo split) ----------------
__global__ void __launch_bounds__(256) gemm1_mma_kernel(const float* __restrict__ X) {
    __shared__ __align__(16) uint8_t Ahi[128 * 128];
    __shared__ __align__(16) uint8_t Alo[128 * 128];

    const int tid  = threadIdx.x;
    const int wid  = tid >> 5;
    const int lane = tid & 31;
    const int m0   = blockIdx.x * 128;
    const int warp_m = (wid >> 1) * 32;
    const int warp_n = (wid & 1) * 64;

    const uint32_t ahi_base = smem_u32(Ahi);
    const uint32_t alo_base = smem_u32(Alo);

    const int arow  = tid >> 1;
    const int ahalf = tid & 1;
    const int gm    = m0 + arow;
    const float* xrow = X + (size_t)gm * D_IN;
    const bool rok = (gm < N_NODES);

    float acc[2][8][4];
    #pragma unroll
    for (int mt = 0; mt < 2; mt++)
        #pragma unroll
        for (int nt = 0; nt < 8; nt++)
            #pragma unroll
            for (int r = 0; r < 4; r++) acc[mt][nt][r] = 0.0f;

    for (int chunk = 0; chunk < 8; chunk++) {
        if (chunk > 0) __syncthreads();
        #pragma unroll
        for (int q = 0; q < 8; q++) {
            int kl = ahalf * 32 + q * 4;
            int kg = chunk * 64 + kl;
            float4 v = make_float4(0.f, 0.f, 0.f, 0.f);
            if (rok && kg < D_IN) v = *(const float4*)(xrow + kg);
            __nv_bfloat16 h0 = __float2bfloat16(v.x);
            __nv_bfloat16 h1 = __float2bfloat16(v.y);
            __nv_bfloat16 h2 = __float2bfloat16(v.z);
            __nv_bfloat16 h3 = __float2bfloat16(v.w);
            __nv_bfloat16 l0 = __float2bfloat16(v.x - __bfloat162float(h0));
            __nv_bfloat16 l1 = __float2bfloat16(v.y - __bfloat162float(h1));
            __nv_bfloat16 l2 = __float2bfloat16(v.z - __bfloat162float(h2));
            __nv_bfloat16 l3 = __float2bfloat16(v.w - __bfloat162float(h3));
            int ch  = kl >> 3;
            int sub = (kl & 7) ? 8 : 0;
            uint32_t off = arow * 128 + ((ch ^ (arow & 7)) << 4) + sub;
            __nv_bfloat162 hp0 = {h0, h1}, hp1 = {h2, h3};
            __nv_bfloat162 lp0 = {l0, l1}, lp1 = {l2, l3};
            uint2 hv = { *(uint32_t*)&hp0, *(uint32_t*)&hp1 };
            uint2 lv = { *(uint32_t*)&lp0, *(uint32_t*)&lp1 };
            *(uint2*)(Ahi + off) = hv;
            *(uint2*)(Alo + off) = lv;
        }
        __syncthreads();

        #pragma unroll
        for (int kstep = 0; kstep < 4; kstep++) {
            int kg = chunk * 4 + kstep;
            uint32_t ah[2][4], al[2][4];
            #pragma unroll
            for (int mt = 0; mt < 2; mt++) {
                int mrow = warp_m + mt * 16 + (lane & 7) + ((lane & 8) ? 8 : 0);
                int ch   = kstep * 2 + (lane >> 4);
                uint32_t off = mrow * 128 + ((ch ^ (mrow & 7)) << 4);
                asm volatile("ldmatrix.sync.aligned.m8n8.x4.shared.b16 {%0,%1,%2,%3}, [%4];"
                             : "=r"(ah[mt][0]), "=r"(ah[mt][1]), "=r"(ah[mt][2]), "=r"(ah[mt][3])
                             : "r"(ahi_base + off));
                asm volatile("ldmatrix.sync.aligned.m8n8.x4.shared.b16 {%0,%1,%2,%3}, [%4];"
                             : "=r"(al[mt][0]), "=r"(al[mt][1]), "=r"(al[mt][2]), "=r"(al[mt][3])
                             : "r"(alo_base + off));
            }
            uint4 bh[4], bl[4];
            #pragma unroll
            for (int p = 0; p < 4; p++) {
                int npair = (warp_n >> 4) + p;
                int idx = kg * 1024 + npair * 128 + lane * 4;
                bh[p] = *(const uint4*)(g_bhi + idx);
                bl[p] = *(const uint4*)(g_blo + idx);
            }
            #pragma unroll
            for (int mt = 0; mt < 2; mt++) {
                #pragma unroll
                for (int nt = 0; nt < 8; nt++) {
                    int p = nt >> 1;
                    uint32_t bh0 = (nt & 1) ? bh[p].z : bh[p].x;
                    uint32_t bh1 = (nt & 1) ? bh[p].w : bh[p].y;
                    uint32_t bl0 = (nt & 1) ? bl[p].z : bl[p].x;
                    uint32_t bl1 = (nt & 1) ? bl[p].w : bl[p].y;
                    float* c = acc[mt][nt];
                    asm volatile("mma.sync.aligned.m16n8k16.row.col.f32.bf16.bf16.f32 "
                        "{%0,%1,%2,%3}, {%4,%5,%6,%7}, {%8,%9}, {%0,%1,%2,%3};"
                        : "+f"(c[0]), "+f"(c[1]), "+f"(c[2]), "+f"(c[3])
                        : "r"(ah[mt][0]), "r"(ah[mt][1]), "r"(ah[mt][2]), "r"(ah[mt][3]),
                          "r"(bh0), "r"(bh1));
                    asm volatile("mma.sync.aligned.m16n8k16.row.col.f32.bf16.bf16.f32 "
                        "{%0,%1,%2,%3}, {%4,%5,%6,%7}, {%8,%9}, {%0,%1,%2,%3};"
                        : "+f"(c[0]), "+f"(c[1]), "+f"(c[2]), "+f"(c[3])
                        : "r"(ah[mt][0]), "r"(ah[mt][1]), "r"(ah[mt][2]), "r"(ah[mt][3]),
                          "r"(bl0), "r"(bl1));
                    asm volatile("mma.sync.aligned.m16n8k16.row.col.f32.bf16.bf16.f32 "
                        "{%0,%1,%2,%3}, {%4,%5,%6,%7}, {%8,%9}, {%0,%1,%2,%3};"
                        : "+f"(c[0]), "+f"(c[1]), "+f"(c[2]), "+f"(c[3])
                        : "r"(al[mt][0]), "r"(al[mt][1]), "r"(al[mt][2]), "r"(al[mt][3]),
                          "r"(bh0), "r"(bh1));
                }
            }
        }
    }

    #pragma unroll
    for (int mt = 0; mt < 2; mt++) {
        int r0 = m0 + warp_m + mt * 16 + (lane >> 2);
        int r1 = r0 + 8;
        float d0 = (r0 < N_NODES) ? g_dinv[r0] : 0.0f;
        float d1 = (r1 < N_NODES) ? g_dinv[r1] : 0.0f;
        #pragma unroll
        for (int nt = 0; nt < 8; nt++) {
            int cc = warp_n + nt * 8 + (lane & 3) * 2;
            if (r0 < N_NODES) {
                float2 o = make_float2(acc[mt][nt][0] * d0, acc[mt][nt][1] * d0);
                *(float2*)&g_hs[(size_t)r0 * D_H + cc] = o;
            }
            if (r1 < N_NODES) {
                float2 o = make_float2(acc[mt][nt][2] * d1, acc[mt][nt][3] * d1);
                *(float2*)&g_hs[(size_t)r1 * D_H + cc] = o;
            }
        }
    }
}

// ---------------- agg1: CSR gather, warp per node, float4 lanes ------------
__global__ void __launch_bounds__(256) agg1_kernel() {
    int w = (blockIdx.x * blockDim.x + threadIdx.x) >> 5;
    int lane = threadIdx.x & 31;
    if (w >= N_NODES) return;
    int start = g_off[w];
    int cnt   = g_cnt[w];
    const float* base = &g_hs[(size_t)lane * 4];
    float4 acc = *(const float4*)&g_hs[(size_t)w * D_H + lane * 4];

    for (int b = 0; b < cnt; b += 32) {
        int n = min(32, cnt - b);
        int src = (lane < n) ? g_csr[start + b + lane] : 0;
        int j = 0;
        for (; j + 4 <= n; j += 4) {
            int s0 = __shfl_sync(0xffffffffu, src, j);
            int s1 = __shfl_sync(0xffffffffu, src, j + 1);
            int s2 = __shfl_sync(0xffffffffu, src, j + 2);
            int s3 = __shfl_sync(0xffffffffu, src, j + 3);
            float4 v0 = *(const float4*)(base + (size_t)s0 * D_H);
            float4 v1 = *(const float4*)(base + (size_t)s1 * D_H);
            float4 v2 = *(const float4*)(base + (size_t)s2 * D_H);
            float4 v3 = *(const float4*)(base + (size_t)s3 * D_H);
            acc.x += (v0.x + v1.x) + (v2.x + v3.x);
            acc.y += (v0.y + v1.y) + (v2.y + v3.y);
            acc.z += (v0.z + v1.z) + (v2.z + v3.z);
            acc.w += (v0.w + v1.w) + (v2.w + v3.w);
        }
        for (; j < n; j++) {
            int s = __shfl_sync(0xffffffffu, src, j);
            float4 v = *(const float4*)(base + (size_t)s * D_H);
            acc.x += v.x; acc.y += v.y; acc.z += v.z; acc.w += v.w;
        }
    }
    *(float4*)&g_acc1[(size_t)w * D_H + lane * 4] = acc;
}

// ---------------- GEMM2: g_hs2 = (relu(b1 + dinv*acc1) @ W2) * dinv --------
__global__ void __launch_bounds__(256) gemm2_kernel(const float* __restrict__ W,
                                                    const float* __restrict__ b1) {
    __shared__ float xs[32][132];
    __shared__ float ws[32][64];
    const int m0  = blockIdx.x * 128;
    const int tid = threadIdx.x;
    const int tx  = tid & 15;
    const int ty  = tid >> 4;

    float acc[8][4];
    #pragma unroll
    for (int i = 0; i < 8; i++)
        #pragma unroll
        for (int j = 0; j < 4; j++) acc[i][j] = 0.0f;

    for (int k0 = 0; k0 < D_H; k0 += 32) {
        #pragma unroll
        for (int it = 0; it < 16; it++) {
            int idx = tid + it * 256;
            int m = idx >> 5, k = idx & 31;
            int gm = m0 + m;
            float v = 0.0f;
            if (gm < N_NODES) {
                float d = g_dinv[gm];
                v = fmaf(g_acc1[(size_t)gm * D_H + k0 + k], d, b1[k0 + k]);
            }
            xs[k][m] = fmaxf(v, 0.0f);
        }
        #pragma unroll
        for (int it = 0; it < 8; it++) {
            int idx = tid + it * 256;
            int k = idx >> 6, n = idx & 63;
            ws[k][n] = W[(size_t)(k0 + k) * D_O + n];
        }
        __syncthreads();

        #pragma unroll
        for (int kk = 0; kk < 32; kk++) {
            float4 a0 = *(const float4*)&xs[kk][ty * 8];
            float4 a1 = *(const float4*)&xs[kk][ty * 8 + 4];
            float4 b  = *(const float4*)&ws[kk][tx * 4];
            float av[8] = {a0.x, a0.y, a0.z, a0.w, a1.x, a1.y, a1.z, a1.w};
            float bv[4] = {b.x, b.y, b.z, b.w};
            #pragma unroll
            for (int i = 0; i < 8; i++)
                #pragma unroll
                for (int j = 0; j < 4; j++)
                    acc[i][j] = fmaf(av[i], bv[j], acc[i][j]);
        }
        __syncthreads();
    }

    #pragma unroll
    for (int i = 0; i < 8; i++) {
        int gm = m0 + ty * 8 + i;
        if (gm < N_NODES) {
            float d = g_dinv[gm];
            float4 o = make_float4(acc[i][0] * d, acc[i][1] * d,
                                   acc[i][2] * d, acc[i][3] * d);
            *(float4*)&g_hs2[(size_t)gm * D_O + tx * 4] = o;
        }
    }
}

// ---------------- agg2: CSR gather, warp per node, float2 lanes ------------
__global__ void __launch_bounds__(256) agg2_kernel(const float* __restrict__ b2) {
    int w = (blockIdx.x * blockDim.x + threadIdx.x) >> 5;
    int lane = threadIdx.x & 31;
    if (w >= N_NODES) return;
    int start = g_off[w];
    int cnt   = g_cnt[w];
    const float* base = &g_hs2[(size_t)lane * 2];
    float2 acc = *(const float2*)&g_hs2[(size_t)w * D_O + lane * 2];

    for (int b = 0; b < cnt; b += 32) {
        int n = min(32, cnt - b);
        int src = (lane < n) ? g_csr[start + b + lane] : 0;
        int j = 0;
        for (; j + 4 <= n; j += 4) {
            int s0 = __shfl_sync(0xffffffffu, src, j);
            int s1 = __shfl_sync(0xffffffffu, src, j + 1);
            int s2 = __shfl_sync(0xffffffffu, src, j + 2);
            int s3 = __shfl_sync(0xffffffffu, src, j + 3);
            float2 v0 = *(const float2*)(base + (size_t)s0 * D_O);
            float2 v1 = *(const float2*)(base + (size_t)s1 * D_O);
            float2 v2 = *(const float2*)(base + (size_t)s2 * D_O);
            float2 v3 = *(const float2*)(base + (size_t)s3 * D_O);
            acc.x += (v0.x + v1.x) + (v2.x + v3.x);
            acc.y += (v0.y + v1.y) + (v2.y + v3.y);
        }
        for (; j < n; j++) {
            int s = __shfl_sync(0xffffffffu, src, j);
            float2 v = *(const float2*)(base + (size_t)s * D_O);
            acc.x += v.x; acc.y += v.y;
        }
    }
    float d = g_dinv[w];
    float2 z = make_float2(fmaf(acc.x, d, b2[lane * 2]),
                           fmaf(acc.y, d, b2[lane * 2 + 1]));
    *(float2*)&g_z[(size_t)w * D_O + lane * 2] = z;
}

// ---------------- decode (CSR order): warp per dst node -------------------
// Half-warp per edge: z[dst] cached in registers, only z[src] gathered.
__global__ void __launch_bounds__(256) decode_csr_kernel(float* __restrict__ out) {
    int w = (blockIdx.x * blockDim.x + threadIdx.x) >> 5;
    int lane = threadIdx.x & 31;
    if (w >= N_NODES) return;
    int start = g_off[w];
    int cnt   = g_cnt[w];
    if (cnt == 0) return;
    int half = lane >> 4;          // 0 or 1: edge slot within pair
    int hl   = lane & 15;          // lane within half-warp

    float4 zc = *(const float4*)&g_z[(size_t)w * D_O + hl * 4];

    for (int b = 0; b < cnt; b += 2) {
        int idx = b + half;
        float s = 0.0f;
        int eid = 0;
        bool ok = (idx < cnt);
        if (ok) {
            int src = g_csr[start + idx];
            eid     = g_eid[start + idx];
            float4 zr = *(const float4*)&g_z[(size_t)src * D_O + hl * 4];
            s = zc.x * zr.x + zc.y * zr.y + zc.z * zr.z + zc.w * zr.w;
        }
        s += __shfl_xor_sync(0xffffffffu, s, 1);
        s += __shfl_xor_sync(0xffffffffu, s, 2);
        s += __shfl_xor_sync(0xffffffffu, s, 4);
        s += __shfl_xor_sync(0xffffffffu, s, 8);
        if (ok && hl == 0) out[eid] = s;
    }
}

// ---------------- launch ----------------
extern "C" void kernel_launch(void* const* d_in, const int* in_sizes, int n_in,
                              void* d_out, int out_size) {
    const float* x  = (const float*)d_in[0];
    const float* W1 = (const float*)d_in[1];
    const float* b1 = (const float*)d_in[2];
    const float* W2 = (const float*)d_in[3];
    const float* b2 = (const float*)d_in[4];
    const int*   ei = (const int*)d_in[5];
    const int E = in_sizes[5] / 2;

    cnt_init_kernel<<<NB1, 256>>>();
    deg_count_kernel<<<(E + 255) / 256, 256>>>(ei + E, E);
    dinv_kernel<<<NB1, 256>>>();
    scan1_kernel<<<NB1, 256>>>();
    scan2_kernel<<<1, 512>>>();
    scan3b_kernel<<<NB1, 256>>>();
    csr_fill_kernel<<<(E + 255) / 256, 256>>>(ei, E);

    w1split_kernel<<<128, 256>>>(W1);
    gemm1_mma_kernel<<<(N_NODES + 127) / 128, 256>>>(x);
    agg1_kernel<<<(N_NODES * 32 + 255) / 256, 256>>>();

    gemm2_kernel<<<(N_NODES + 127) / 128, 256>>>(W2, b1);
    agg2_kernel<<<(N_NODES * 32 + 255) / 256, 256>>>(b2);

    decode_csr_kernel<<<(N_NODES * 32 + 255) / 256, 256>>>((float*)d_out);
}

// round 8
// speedup vs baseline: 2.4685x; 1.0654x over previous
#include <cuda_runtime.h>
#include <cuda_bf16.h>
#include <cstdint>

#define N_NODES 100000
#define D_IN    500
#define D_H     128
#define D_O     64
#define E_MAX   3200000
#define NB1     ((N_NODES + 255) / 256)

// ---------------- scratch ----------------
__device__ int   g_cnt [N_NODES];
__device__ float g_dinv[N_NODES];
__device__ int   g_off [N_NODES];
__device__ int   g_cur [N_NODES];
__device__ int   g_part[512];
__device__ int2  g_cse [E_MAX];   // (src, eid) per in-edge, grouped by dst
// W1^T bf16 hi/lo pre-packed in mma.m16n8k16 B-fragment order:
__device__ __align__(16) uint32_t g_bhi[32 * 1024];
__device__ __align__(16) uint32_t g_blo[32 * 1024];
__device__ float g_hs  [(size_t)N_NODES * D_H];
__device__ float g_acc1[(size_t)N_NODES * D_H];
__device__ float g_hs2 [(size_t)N_NODES * D_O];
__device__ float g_z   [(size_t)N_NODES * D_O];

__device__ __forceinline__ uint32_t smem_u32(const void* p) {
    uint32_t a;
    asm("{ .reg .u64 t; cvta.to.shared.u64 t, %1; cvt.u32.u64 %0, t; }"
        : "=r"(a) : "l"(p));
    return a;
}

// ---------------- degree / CSR ----------------
__global__ void cnt_init_kernel() {
    int i = blockIdx.x * blockDim.x + threadIdx.x;
    if (i < N_NODES) g_cnt[i] = 0;
}
__global__ void deg_count_kernel(const int* __restrict__ col, int E) {
    int e = blockIdx.x * blockDim.x + threadIdx.x;
    if (e < E) atomicAdd(&g_cnt[col[e]], 1);
}
__global__ void dinv_kernel() {
    int i = blockIdx.x * blockDim.x + threadIdx.x;
    if (i < N_NODES) g_dinv[i] = rsqrtf((float)(g_cnt[i] + 1));
}
__global__ void scan1_kernel() {
    __shared__ int s[256];
    int tid = threadIdx.x;
    int i = blockIdx.x * 256 + tid;
    int v = (i < N_NODES) ? g_cnt[i] : 0;
    s[tid] = v;
    __syncthreads();
    #pragma unroll
    for (int d = 1; d < 256; d <<= 1) {
        int t = (tid >= d) ? s[tid - d] : 0;
        __syncthreads();
        s[tid] += t;
        __syncthreads();
    }
    if (i < N_NODES) g_off[i] = s[tid] - v;
    if (tid == 255) g_part[blockIdx.x] = s[255];
}
__global__ void scan2_kernel() {
    __shared__ int s[512];
    int tid = threadIdx.x;
    int v = (tid < NB1) ? g_part[tid] : 0;
    s[tid] = v;
    __syncthreads();
    #pragma unroll
    for (int d = 1; d < 512; d <<= 1) {
        int t = (tid >= d) ? s[tid - d] : 0;
        __syncthreads();
        s[tid] += t;
        __syncthreads();
    }
    if (tid < NB1) g_part[tid] = s[tid] - v;
}
__global__ void scan3b_kernel() {
    int i = blockIdx.x * blockDim.x + threadIdx.x;
    if (i < N_NODES) {
        g_off[i] += g_part[i >> 8];
        g_cur[i] = 0;
    }
}
__global__ void csr_fill_kernel(const int* __restrict__ ei, int E) {
    int e = blockIdx.x * blockDim.x + threadIdx.x;
    if (e >= E) return;
    int r = ei[e];
    int c = ei[E + e];
    int pos = g_off[c] + atomicAdd(&g_cur[c], 1);
    g_cse[pos] = make_int2(r, e);
}

// ---------------- W1 split into mma B fragments ----------------
__global__ void w1split_kernel(const float* __restrict__ W1) {
    int i = blockIdx.x * blockDim.x + threadIdx.x;   // 32768
    if (i >= 32768) return;
    int reg   = i & 1;
    int lane  = (i >> 1) & 31;
    int ntile = (i >> 6) & 15;
    int kstep = i >> 10;
    int n = ntile * 8 + (lane >> 2);
    int k = kstep * 16 + reg * 8 + (lane & 3) * 2;

    float w0 = (k     < D_IN) ? W1[(size_t)k * D_H + n]       : 0.0f;
    float w1 = (k + 1 < D_IN) ? W1[(size_t)(k + 1) * D_H + n] : 0.0f;
    __nv_bfloat16 h0 = __float2bfloat16(w0);
    __nv_bfloat16 h1 = __float2bfloat16(w1);
    __nv_bfloat16 l0 = __float2bfloat16(w0 - __bfloat162float(h0));
    __nv_bfloat16 l1 = __float2bfloat16(w1 - __bfloat162float(h1));
    __nv_bfloat162 hp = {h0, h1}, lp = {l0, l1};

    int idx = kstep * 1024 + (ntile >> 1) * 128 + lane * 4 + (ntile & 1) * 2 + reg;
    g_bhi[idx] = *(uint32_t*)&hp;
    g_blo[idx] = *(uint32_t*)&lp;
}

// ---------------- GEMM1 (mma.sync bf16 hi/lo split) ----------------
__global__ void __launch_bounds__(256) gemm1_mma_kernel(const float* __restrict__ X) {
    __shared__ __align__(16) uint8_t Ahi[128 * 128];
    __shared__ __align__(16) uint8_t Alo[128 * 128];

    const int tid  = threadIdx.x;
    const int wid  = tid >> 5;
    const int lane = tid & 31;
    const int m0   = blockIdx.x * 128;
    const int warp_m = (wid >> 1) * 32;
    const int warp_n = (wid & 1) * 64;

    const uint32_t ahi_base = smem_u32(Ahi);
    const uint32_t alo_base = smem_u32(Alo);

    const int arow  = tid >> 1;
    const int ahalf = tid & 1;
    const int gm    = m0 + arow;
    const float* xrow = X + (size_t)gm * D_IN;
    const bool rok = (gm < N_NODES);

    float acc[2][8][4];
    #pragma unroll
    for (int mt = 0; mt < 2; mt++)
        #pragma unroll
        for (int nt = 0; nt < 8; nt++)
            #pragma unroll
            for (int r = 0; r < 4; r++) acc[mt][nt][r] = 0.0f;

    for (int chunk = 0; chunk < 8; chunk++) {
        if (chunk > 0) __syncthreads();
        #pragma unroll
        for (int q = 0; q < 8; q++) {
            int kl = ahalf * 32 + q * 4;
            int kg = chunk * 64 + kl;
            float4 v = make_float4(0.f, 0.f, 0.f, 0.f);
            if (rok && kg < D_IN) v = *(const float4*)(xrow + kg);
            __nv_bfloat16 h0 = __float2bfloat16(v.x);
            __nv_bfloat16 h1 = __float2bfloat16(v.y);
            __nv_bfloat16 h2 = __float2bfloat16(v.z);
            __nv_bfloat16 h3 = __float2bfloat16(v.w);
            __nv_bfloat16 l0 = __float2bfloat16(v.x - __bfloat162float(h0));
            __nv_bfloat16 l1 = __float2bfloat16(v.y - __bfloat162float(h1));
            __nv_bfloat16 l2 = __float2bfloat16(v.z - __bfloat162float(h2));
            __nv_bfloat16 l3 = __float2bfloat16(v.w - __bfloat162float(h3));
            int ch  = kl >> 3;
            int sub = (kl & 7) ? 8 : 0;
            uint32_t off = arow * 128 + ((ch ^ (arow & 7)) << 4) + sub;
            __nv_bfloat162 hp0 = {h0, h1}, hp1 = {h2, h3};
            __nv_bfloat162 lp0 = {l0, l1}, lp1 = {l2, l3};
            uint2 hv = { *(uint32_t*)&hp0, *(uint32_t*)&hp1 };
            uint2 lv = { *(uint32_t*)&lp0, *(uint32_t*)&lp1 };
            *(uint2*)(Ahi + off) = hv;
            *(uint2*)(Alo + off) = lv;
        }
        __syncthreads();

        #pragma unroll
        for (int kstep = 0; kstep < 4; kstep++) {
            int kg = chunk * 4 + kstep;
            uint32_t ah[2][4], al[2][4];
            #pragma unroll
            for (int mt = 0; mt < 2; mt++) {
                int mrow = warp_m + mt * 16 + (lane & 7) + ((lane & 8) ? 8 : 0);
                int ch   = kstep * 2 + (lane >> 4);
                uint32_t off = mrow * 128 + ((ch ^ (mrow & 7)) << 4);
                asm volatile("ldmatrix.sync.aligned.m8n8.x4.shared.b16 {%0,%1,%2,%3}, [%4];"
                             : "=r"(ah[mt][0]), "=r"(ah[mt][1]), "=r"(ah[mt][2]), "=r"(ah[mt][3])
                             : "r"(ahi_base + off));
                asm volatile("ldmatrix.sync.aligned.m8n8.x4.shared.b16 {%0,%1,%2,%3}, [%4];"
                             : "=r"(al[mt][0]), "=r"(al[mt][1]), "=r"(al[mt][2]), "=r"(al[mt][3])
                             : "r"(alo_base + off));
            }
            uint4 bh[4], bl[4];
            #pragma unroll
            for (int p = 0; p < 4; p++) {
                int npair = (warp_n >> 4) + p;
                int idx = kg * 1024 + npair * 128 + lane * 4;
                bh[p] = *(const uint4*)(g_bhi + idx);
                bl[p] = *(const uint4*)(g_blo + idx);
            }
            #pragma unroll
            for (int mt = 0; mt < 2; mt++) {
                #pragma unroll
                for (int nt = 0; nt < 8; nt++) {
                    int p = nt >> 1;
                    uint32_t bh0 = (nt & 1) ? bh[p].z : bh[p].x;
                    uint32_t bh1 = (nt & 1) ? bh[p].w : bh[p].y;
                    uint32_t bl0 = (nt & 1) ? bl[p].z : bl[p].x;
                    uint32_t bl1 = (nt & 1) ? bl[p].w : bl[p].y;
                    float* c = acc[mt][nt];
                    asm volatile("mma.sync.aligned.m16n8k16.row.col.f32.bf16.bf16.f32 "
                        "{%0,%1,%2,%3}, {%4,%5,%6,%7}, {%8,%9}, {%0,%1,%2,%3};"
                        : "+f"(c[0]), "+f"(c[1]), "+f"(c[2]), "+f"(c[3])
                        : "r"(ah[mt][0]), "r"(ah[mt][1]), "r"(ah[mt][2]), "r"(ah[mt][3]),
                          "r"(bh0), "r"(bh1));
                    asm volatile("mma.sync.aligned.m16n8k16.row.col.f32.bf16.bf16.f32 "
                        "{%0,%1,%2,%3}, {%4,%5,%6,%7}, {%8,%9}, {%0,%1,%2,%3};"
                        : "+f"(c[0]), "+f"(c[1]), "+f"(c[2]), "+f"(c[3])
                        : "r"(ah[mt][0]), "r"(ah[mt][1]), "r"(ah[mt][2]), "r"(ah[mt][3]),
                          "r"(bl0), "r"(bl1));
                    asm volatile("mma.sync.aligned.m16n8k16.row.col.f32.bf16.bf16.f32 "
                        "{%0,%1,%2,%3}, {%4,%5,%6,%7}, {%8,%9}, {%0,%1,%2,%3};"
                        : "+f"(c[0]), "+f"(c[1]), "+f"(c[2]), "+f"(c[3])
                        : "r"(al[mt][0]), "r"(al[mt][1]), "r"(al[mt][2]), "r"(al[mt][3]),
                          "r"(bh0), "r"(bh1));
                }
            }
        }
    }

    #pragma unroll
    for (int mt = 0; mt < 2; mt++) {
        int r0 = m0 + warp_m + mt * 16 + (lane >> 2);
        int r1 = r0 + 8;
        float d0 = (r0 < N_NODES) ? g_dinv[r0] : 0.0f;
        float d1 = (r1 < N_NODES) ? g_dinv[r1] : 0.0f;
        #pragma unroll
        for (int nt = 0; nt < 8; nt++) {
            int cc = warp_n + nt * 8 + (lane & 3) * 2;
            if (r0 < N_NODES) {
                float2 o = make_float2(acc[mt][nt][0] * d0, acc[mt][nt][1] * d0);
                *(float2*)&g_hs[(size_t)r0 * D_H + cc] = o;
            }
            if (r1 < N_NODES) {
                float2 o = make_float2(acc[mt][nt][2] * d1, acc[mt][nt][3] * d1);
                *(float2*)&g_hs[(size_t)r1 * D_H + cc] = o;
            }
        }
    }
}

// ---------------- agg1: CSR gather, warp per node, float4 lanes ------------
__global__ void __launch_bounds__(256) agg1_kernel() {
    int w = (blockIdx.x * blockDim.x + threadIdx.x) >> 5;
    int lane = threadIdx.x & 31;
    if (w >= N_NODES) return;
    int start = g_off[w];
    int cnt   = g_cnt[w];
    const float* base = &g_hs[(size_t)lane * 4];
    float4 acc = *(const float4*)&g_hs[(size_t)w * D_H + lane * 4];

    for (int b = 0; b < cnt; b += 32) {
        int n = min(32, cnt - b);
        int src = (lane < n) ? g_cse[start + b + lane].x : 0;
        int j = 0;
        for (; j + 4 <= n; j += 4) {
            int s0 = __shfl_sync(0xffffffffu, src, j);
            int s1 = __shfl_sync(0xffffffffu, src, j + 1);
            int s2 = __shfl_sync(0xffffffffu, src, j + 2);
            int s3 = __shfl_sync(0xffffffffu, src, j + 3);
            float4 v0 = *(const float4*)(base + (size_t)s0 * D_H);
            float4 v1 = *(const float4*)(base + (size_t)s1 * D_H);
            float4 v2 = *(const float4*)(base + (size_t)s2 * D_H);
            float4 v3 = *(const float4*)(base + (size_t)s3 * D_H);
            acc.x += (v0.x + v1.x) + (v2.x + v3.x);
            acc.y += (v0.y + v1.y) + (v2.y + v3.y);
            acc.z += (v0.z + v1.z) + (v2.z + v3.z);
            acc.w += (v0.w + v1.w) + (v2.w + v3.w);
        }
        for (; j < n; j++) {
            int s = __shfl_sync(0xffffffffu, src, j);
            float4 v = *(const float4*)(base + (size_t)s * D_H);
            acc.x += v.x; acc.y += v.y; acc.z += v.z; acc.w += v.w;
        }
    }
    *(float4*)&g_acc1[(size_t)w * D_H + lane * 4] = acc;
}

// ---------------- GEMM2: g_hs2 = (relu(b1 + dinv*acc1) @ W2) * dinv --------
__global__ void __launch_bounds__(256) gemm2_kernel(const float* __restrict__ W,
                                                    const float* __restrict__ b1) {
    __shared__ float xs[32][132];
    __shared__ float ws[32][64];
    const int m0  = blockIdx.x * 128;
    const int tid = threadIdx.x;
    const int tx  = tid & 15;
    const int ty  = tid >> 4;

    float acc[8][4];
    #pragma unroll
    for (int i = 0; i < 8; i++)
        #pragma unroll
        for (int j = 0; j < 4; j++) acc[i][j] = 0.0f;

    for (int k0 = 0; k0 < D_H; k0 += 32) {
        #pragma unroll
        for (int it = 0; it < 16; it++) {
            int idx = tid + it * 256;
            int m = idx >> 5, k = idx & 31;
            int gm = m0 + m;
            float v = 0.0f;
            if (gm < N_NODES) {
                float d = g_dinv[gm];
                v = fmaf(g_acc1[(size_t)gm * D_H + k0 + k], d, b1[k0 + k]);
            }
            xs[k][m] = fmaxf(v, 0.0f);
        }
        #pragma unroll
        for (int it = 0; it < 8; it++) {
            int idx = tid + it * 256;
            int k = idx >> 6, n = idx & 63;
            ws[k][n] = W[(size_t)(k0 + k) * D_O + n];
        }
        __syncthreads();

        #pragma unroll
        for (int kk = 0; kk < 32; kk++) {
            float4 a0 = *(const float4*)&xs[kk][ty * 8];
            float4 a1 = *(const float4*)&xs[kk][ty * 8 + 4];
            float4 b  = *(const float4*)&ws[kk][tx * 4];
            float av[8] = {a0.x, a0.y, a0.z, a0.w, a1.x, a1.y, a1.z, a1.w};
            float bv[4] = {b.x, b.y, b.z, b.w};
            #pragma unroll
            for (int i = 0; i < 8; i++)
                #pragma unroll
                for (int j = 0; j < 4; j++)
                    acc[i][j] = fmaf(av[i], bv[j], acc[i][j]);
        }
        __syncthreads();
    }

    #pragma unroll
    for (int i = 0; i < 8; i++) {
        int gm = m0 + ty * 8 + i;
        if (gm < N_NODES) {
            float d = g_dinv[gm];
            float4 o = make_float4(acc[i][0] * d, acc[i][1] * d,
                                   acc[i][2] * d, acc[i][3] * d);
            *(float4*)&g_hs2[(size_t)gm * D_O + tx * 4] = o;
        }
    }
}

// ---------------- agg2: CSR gather, warp per node, float2 lanes ------------
__global__ void __launch_bounds__(256) agg2_kernel(const float* __restrict__ b2) {
    int w = (blockIdx.x * blockDim.x + threadIdx.x) >> 5;
    int lane = threadIdx.x & 31;
    if (w >= N_NODES) return;
    int start = g_off[w];
    int cnt   = g_cnt[w];
    const float* base = &g_hs2[(size_t)lane * 2];
    float2 acc = *(const float2*)&g_hs2[(size_t)w * D_O + lane * 2];

    for (int b = 0; b < cnt; b += 32) {
        int n = min(32, cnt - b);
        int src = (lane < n) ? g_cse[start + b + lane].x : 0;
        int j = 0;
        for (; j + 4 <= n; j += 4) {
            int s0 = __shfl_sync(0xffffffffu, src, j);
            int s1 = __shfl_sync(0xffffffffu, src, j + 1);
            int s2 = __shfl_sync(0xffffffffu, src, j + 2);
            int s3 = __shfl_sync(0xffffffffu, src, j + 3);
            float2 v0 = *(const float2*)(base + (size_t)s0 * D_O);
            float2 v1 = *(const float2*)(base + (size_t)s1 * D_O);
            float2 v2 = *(const float2*)(base + (size_t)s2 * D_O);
            float2 v3 = *(const float2*)(base + (size_t)s3 * D_O);
            acc.x += (v0.x + v1.x) + (v2.x + v3.x);
            acc.y += (v0.y + v1.y) + (v2.y + v3.y);
        }
        for (; j < n; j++) {
            int s = __shfl_sync(0xffffffffu, src, j);
            float2 v = *(const float2*)(base + (size_t)s * D_O);
            acc.x += v.x; acc.y += v.y;
        }
    }
    float d = g_dinv[w];
    float2 z = make_float2(fmaf(acc.x, d, b2[lane * 2]),
                           fmaf(acc.y, d, b2[lane * 2 + 1]));
    *(float2*)&g_z[(size_t)w * D_O + lane * 2] = z;
}

// ---------------- decode (CSR order): warp per dst node -------------------
__global__ void __launch_bounds__(256) decode_csr_kernel(float* __restrict__ out) {
    int w = (blockIdx.x * blockDim.x + threadIdx.x) >> 5;
    int lane = threadIdx.x & 31;
    if (w >= N_NODES) return;
    int start = g_off[w];
    int cnt   = g_cnt[w];
    if (cnt == 0) return;
    int half = lane >> 4;
    int hl   = lane & 15;

    float4 zc = *(const float4*)&g_z[(size_t)w * D_O + hl * 4];

    for (int b = 0; b < cnt; b += 2) {
        int idx = b + half;
        float s = 0.0f;
        int eid = 0;
        bool ok = (idx < cnt);
        if (ok) {
            int2 se = g_cse[start + idx];
            eid = se.y;
            float4 zr = *(const float4*)&g_z[(size_t)se.x * D_O + hl * 4];
            s = zc.x * zr.x + zc.y * zr.y + zc.z * zr.z + zc.w * zr.w;
        }
        s += __shfl_xor_sync(0xffffffffu, s, 1);
        s += __shfl_xor_sync(0xffffffffu, s, 2);
        s += __shfl_xor_sync(0xffffffffu, s, 4);
        s += __shfl_xor_sync(0xffffffffu, s, 8);
        if (ok && hl == 0) out[eid] = s;
    }
}

// ---------------- launch ----------------
extern "C" void kernel_launch(void* const* d_in, const int* in_sizes, int n_in,
                              void* d_out, int out_size) {
    const float* x  = (const float*)d_in[0];
    const float* W1 = (const float*)d_in[1];
    const float* b1 = (const float*)d_in[2];
    const float* W2 = (const float*)d_in[3];
    const float* b2 = (const float*)d_in[4];
    const int*   ei = (const int*)d_in[5];
    const int E = in_sizes[5] / 2;

    static cudaStream_t s2 = nullptr;
    static cudaEvent_t evFork = nullptr, evDinv = nullptr, evCsr = nullptr;
    if (!s2) {
        cudaStreamCreateWithFlags(&s2, cudaStreamNonBlocking);
        cudaEventCreateWithFlags(&evFork, cudaEventDisableTiming);
        cudaEventCreateWithFlags(&evDinv, cudaEventDisableTiming);
        cudaEventCreateWithFlags(&evCsr,  cudaEventDisableTiming);
    }

    // fork: CSR chain on s2
    cudaEventRecord(evFork, 0);
    cudaStreamWaitEvent(s2, evFork, 0);

    cnt_init_kernel<<<NB1, 256, 0, s2>>>();
    deg_count_kernel<<<(E + 255) / 256, 256, 0, s2>>>(ei + E, E);
    dinv_kernel<<<NB1, 256, 0, s2>>>();
    cudaEventRecord(evDinv, s2);
    scan1_kernel<<<NB1, 256, 0, s2>>>();
    scan2_kernel<<<1, 512, 0, s2>>>();
    scan3b_kernel<<<NB1, 256, 0, s2>>>();
    csr_fill_kernel<<<(E + 255) / 256, 256, 0, s2>>>(ei, E);
    cudaEventRecord(evCsr, s2);

    // main stream: W1 prep (independent), then gemm1 (needs dinv only)
    w1split_kernel<<<128, 256>>>(W1);
    cudaStreamWaitEvent(0, evDinv, 0);
    gemm1_mma_kernel<<<(N_NODES + 127) / 128, 256>>>(x);

    // join: aggregation needs CSR
    cudaStreamWaitEvent(0, evCsr, 0);
    agg1_kernel<<<(N_NODES * 32 + 255) / 256, 256>>>();

    gemm2_kernel<<<(N_NODES + 127) / 128, 256>>>(W2, b1);
    agg2_kernel<<<(N_NODES * 32 + 255) / 256, 256>>>(b2);

    decode_csr_kernel<<<(N_NODES * 32 + 255) / 256, 256>>>((float*)d_out);
}

// round 9
// speedup vs baseline: 2.5894x; 1.0490x over previous
#include <cuda_runtime.h>
#include <cuda_bf16.h>
#include <cstdint>

#define N_NODES 100000
#define D_IN    500
#define D_H     128
#define D_O     64
#define E_MAX   3200000
#define NB1     ((N_NODES + 255) / 256)

// ---------------- scratch ----------------
__device__ int   g_cnt [N_NODES];
__device__ float g_dinv[N_NODES];
__device__ int   g_off [N_NODES];
__device__ int   g_cur [N_NODES];
__device__ int   g_part[512];
__device__ int2  g_cse [E_MAX];   // (src, eid) per in-edge, grouped by dst
// W^T bf16 hi/lo pre-packed in mma.m16n8k16 B-fragment order
__device__ __align__(16) uint32_t g_bhi[32 * 1024];   // W1: 32 ksteps x 1024
__device__ __align__(16) uint32_t g_blo[32 * 1024];
__device__ __align__(16) uint32_t g_b2hi[8 * 512];    // W2: 8 ksteps x 512
__device__ __align__(16) uint32_t g_b2lo[8 * 512];
__device__ float g_hs  [(size_t)N_NODES * D_H];
__device__ float g_acc1[(size_t)N_NODES * D_H];
__device__ float g_hs2 [(size_t)N_NODES * D_O];
__device__ float g_z   [(size_t)N_NODES * D_O];

__device__ __forceinline__ uint32_t smem_u32(const void* p) {
    uint32_t a;
    asm("{ .reg .u64 t; cvta.to.shared.u64 t, %1; cvt.u32.u64 %0, t; }"
        : "=r"(a) : "l"(p));
    return a;
}

// ---------------- degree / CSR ----------------
__global__ void cnt_init_kernel() {
    int i = blockIdx.x * blockDim.x + threadIdx.x;
    if (i < N_NODES) g_cnt[i] = 0;
}
__global__ void deg_count_kernel(const int* __restrict__ col, int E) {
    int e = blockIdx.x * blockDim.x + threadIdx.x;
    if (e < E) atomicAdd(&g_cnt[col[e]], 1);
}
__global__ void dinv_kernel() {
    int i = blockIdx.x * blockDim.x + threadIdx.x;
    if (i < N_NODES) g_dinv[i] = rsqrtf((float)(g_cnt[i] + 1));
}
__global__ void scan1_kernel() {
    __shared__ int s[256];
    int tid = threadIdx.x;
    int i = blockIdx.x * 256 + tid;
    int v = (i < N_NODES) ? g_cnt[i] : 0;
    s[tid] = v;
    __syncthreads();
    #pragma unroll
    for (int d = 1; d < 256; d <<= 1) {
        int t = (tid >= d) ? s[tid - d] : 0;
        __syncthreads();
        s[tid] += t;
        __syncthreads();
    }
    if (i < N_NODES) g_off[i] = s[tid] - v;
    if (tid == 255) g_part[blockIdx.x] = s[255];
}
__global__ void scan2_kernel() {
    __shared__ int s[512];
    int tid = threadIdx.x;
    int v = (tid < NB1) ? g_part[tid] : 0;
    s[tid] = v;
    __syncthreads();
    #pragma unroll
    for (int d = 1; d < 512; d <<= 1) {
        int t = (tid >= d) ? s[tid - d] : 0;
        __syncthreads();
        s[tid] += t;
        __syncthreads();
    }
    if (tid < NB1) g_part[tid] = s[tid] - v;
}
__global__ void scan3b_kernel() {
    int i = blockIdx.x * blockDim.x + threadIdx.x;
    if (i < N_NODES) {
        g_off[i] += g_part[i >> 8];
        g_cur[i] = 0;
    }
}
__global__ void csr_fill_kernel(const int* __restrict__ ei, int E) {
    int e = blockIdx.x * blockDim.x + threadIdx.x;
    if (e >= E) return;
    int r = ei[e];
    int c = ei[E + e];
    int pos = g_off[c] + atomicAdd(&g_cur[c], 1);
    g_cse[pos] = make_int2(r, e);
}

// ---------------- W1 split into mma B fragments ----------------
__global__ void w1split_kernel(const float* __restrict__ W1) {
    int i = blockIdx.x * blockDim.x + threadIdx.x;   // 32768
    if (i >= 32768) return;
    int reg   = i & 1;
    int lane  = (i >> 1) & 31;
    int ntile = (i >> 6) & 15;
    int kstep = i >> 10;
    int n = ntile * 8 + (lane >> 2);
    int k = kstep * 16 + reg * 8 + (lane & 3) * 2;

    float w0 = (k     < D_IN) ? W1[(size_t)k * D_H + n]       : 0.0f;
    float w1 = (k + 1 < D_IN) ? W1[(size_t)(k + 1) * D_H + n] : 0.0f;
    __nv_bfloat16 h0 = __float2bfloat16(w0);
    __nv_bfloat16 h1 = __float2bfloat16(w1);
    __nv_bfloat16 l0 = __float2bfloat16(w0 - __bfloat162float(h0));
    __nv_bfloat16 l1 = __float2bfloat16(w1 - __bfloat162float(h1));
    __nv_bfloat162 hp = {h0, h1}, lp = {l0, l1};

    int idx = kstep * 1024 + (ntile >> 1) * 128 + lane * 4 + (ntile & 1) * 2 + reg;
    g_bhi[idx] = *(uint32_t*)&hp;
    g_blo[idx] = *(uint32_t*)&lp;
}

// ---------------- W2 split into mma B fragments (K=128, N=64) --------------
__global__ void w2split_kernel(const float* __restrict__ W2) {
    int i = blockIdx.x * blockDim.x + threadIdx.x;   // 8*8*32*2 = 4096
    if (i >= 4096) return;
    int reg   = i & 1;
    int lane  = (i >> 1) & 31;
    int ntile = (i >> 6) & 7;
    int kstep = i >> 9;
    int n = ntile * 8 + (lane >> 2);
    int k = kstep * 16 + reg * 8 + (lane & 3) * 2;

    float w0 = W2[(size_t)k * D_O + n];
    float w1 = W2[(size_t)(k + 1) * D_O + n];
    __nv_bfloat16 h0 = __float2bfloat16(w0);
    __nv_bfloat16 h1 = __float2bfloat16(w1);
    __nv_bfloat16 l0 = __float2bfloat16(w0 - __bfloat162float(h0));
    __nv_bfloat16 l1 = __float2bfloat16(w1 - __bfloat162float(h1));
    __nv_bfloat162 hp = {h0, h1}, lp = {l0, l1};

    int idx = kstep * 512 + (ntile >> 1) * 128 + lane * 4 + (ntile & 1) * 2 + reg;
    g_b2hi[idx] = *(uint32_t*)&hp;
    g_b2lo[idx] = *(uint32_t*)&lp;
}

// ---------------- GEMM1 (mma.sync bf16 hi/lo split, reg-prefetch) ----------
__global__ void __launch_bounds__(256) gemm1_mma_kernel(const float* __restrict__ X) {
    __shared__ __align__(16) uint8_t Ahi[128 * 128];
    __shared__ __align__(16) uint8_t Alo[128 * 128];

    const int tid  = threadIdx.x;
    const int wid  = tid >> 5;
    const int lane = tid & 31;
    const int m0   = blockIdx.x * 128;
    const int warp_m = (wid >> 1) * 32;
    const int warp_n = (wid & 1) * 64;

    const uint32_t ahi_base = smem_u32(Ahi);
    const uint32_t alo_base = smem_u32(Alo);

    const int arow  = tid >> 1;
    const int ahalf = tid & 1;
    const int gm    = m0 + arow;
    const float* xrow = X + (size_t)gm * D_IN;
    const bool rok = (gm < N_NODES);

    float acc[2][8][4];
    #pragma unroll
    for (int mt = 0; mt < 2; mt++)
        #pragma unroll
        for (int nt = 0; nt < 8; nt++)
            #pragma unroll
            for (int r = 0; r < 4; r++) acc[mt][nt][r] = 0.0f;

    float4 px[8];
    #pragma unroll
    for (int q = 0; q < 8; q++) {
        int kg = ahalf * 32 + q * 4;
        px[q] = make_float4(0.f, 0.f, 0.f, 0.f);
        if (rok && kg < D_IN) px[q] = *(const float4*)(xrow + kg);
    }

    for (int chunk = 0; chunk < 8; chunk++) {
        if (chunk > 0) __syncthreads();
        // convert prefetched chunk -> smem
        #pragma unroll
        for (int q = 0; q < 8; q++) {
            int kl = ahalf * 32 + q * 4;
            float4 v = px[q];
            __nv_bfloat16 h0 = __float2bfloat16(v.x);
            __nv_bfloat16 h1 = __float2bfloat16(v.y);
            __nv_bfloat16 h2 = __float2bfloat16(v.z);
            __nv_bfloat16 h3 = __float2bfloat16(v.w);
            __nv_bfloat16 l0 = __float2bfloat16(v.x - __bfloat162float(h0));
            __nv_bfloat16 l1 = __float2bfloat16(v.y - __bfloat162float(h1));
            __nv_bfloat16 l2 = __float2bfloat16(v.z - __bfloat162float(h2));
            __nv_bfloat16 l3 = __float2bfloat16(v.w - __bfloat162float(h3));
            int ch  = kl >> 3;
            int sub = (kl & 7) ? 8 : 0;
            uint32_t off = arow * 128 + ((ch ^ (arow & 7)) << 4) + sub;
            __nv_bfloat162 hp0 = {h0, h1}, hp1 = {h2, h3};
            __nv_bfloat162 lp0 = {l0, l1}, lp1 = {l2, l3};
            uint2 hv = { *(uint32_t*)&hp0, *(uint32_t*)&hp1 };
            uint2 lv = { *(uint32_t*)&lp0, *(uint32_t*)&lp1 };
            *(uint2*)(Ahi + off) = hv;
            *(uint2*)(Alo + off) = lv;
        }
        // prefetch next chunk while MMAs run
        if (chunk < 7) {
            #pragma unroll
            for (int q = 0; q < 8; q++) {
                int kg = (chunk + 1) * 64 + ahalf * 32 + q * 4;
                px[q] = make_float4(0.f, 0.f, 0.f, 0.f);
                if (rok && kg < D_IN) px[q] = *(const float4*)(xrow + kg);
            }
        }
        __syncthreads();

        #pragma unroll
        for (int kstep = 0; kstep < 4; kstep++) {
            int kg = chunk * 4 + kstep;
            uint32_t ah[2][4], al[2][4];
            #pragma unroll
            for (int mt = 0; mt < 2; mt++) {
                int mrow = warp_m + mt * 16 + (lane & 7) + ((lane & 8) ? 8 : 0);
                int ch   = kstep * 2 + (lane >> 4);
                uint32_t off = mrow * 128 + ((ch ^ (mrow & 7)) << 4);
                asm volatile("ldmatrix.sync.aligned.m8n8.x4.shared.b16 {%0,%1,%2,%3}, [%4];"
                             : "=r"(ah[mt][0]), "=r"(ah[mt][1]), "=r"(ah[mt][2]), "=r"(ah[mt][3])
                             : "r"(ahi_base + off));
                asm volatile("ldmatrix.sync.aligned.m8n8.x4.shared.b16 {%0,%1,%2,%3}, [%4];"
                             : "=r"(al[mt][0]), "=r"(al[mt][1]), "=r"(al[mt][2]), "=r"(al[mt][3])
                             : "r"(alo_base + off));
            }
            uint4 bh[4], bl[4];
            #pragma unroll
            for (int p = 0; p < 4; p++) {
                int npair = (warp_n >> 4) + p;
                int idx = kg * 1024 + npair * 128 + lane * 4;
                bh[p] = *(const uint4*)(g_bhi + idx);
                bl[p] = *(const uint4*)(g_blo + idx);
            }
            #pragma unroll
            for (int mt = 0; mt < 2; mt++) {
                #pragma unroll
                for (int nt = 0; nt < 8; nt++) {
                    int p = nt >> 1;
                    uint32_t bh0 = (nt & 1) ? bh[p].z : bh[p].x;
                    uint32_t bh1 = (nt & 1) ? bh[p].w : bh[p].y;
                    uint32_t bl0 = (nt & 1) ? bl[p].z : bl[p].x;
                    uint32_t bl1 = (nt & 1) ? bl[p].w : bl[p].y;
                    float* c = acc[mt][nt];
                    asm volatile("mma.sync.aligned.m16n8k16.row.col.f32.bf16.bf16.f32 "
                        "{%0,%1,%2,%3}, {%4,%5,%6,%7}, {%8,%9}, {%0,%1,%2,%3};"
                        : "+f"(c[0]), "+f"(c[1]), "+f"(c[2]), "+f"(c[3])
                        : "r"(ah[mt][0]), "r"(ah[mt][1]), "r"(ah[mt][2]), "r"(ah[mt][3]),
                          "r"(bh0), "r"(bh1));
                    asm volatile("mma.sync.aligned.m16n8k16.row.col.f32.bf16.bf16.f32 "
                        "{%0,%1,%2,%3}, {%4,%5,%6,%7}, {%8,%9}, {%0,%1,%2,%3};"
                        : "+f"(c[0]), "+f"(c[1]), "+f"(c[2]), "+f"(c[3])
                        : "r"(ah[mt][0]), "r"(ah[mt][1]), "r"(ah[mt][2]), "r"(ah[mt][3]),
                          "r"(bl0), "r"(bl1));
                    asm volatile("mma.sync.aligned.m16n8k16.row.col.f32.bf16.bf16.f32 "
                        "{%0,%1,%2,%3}, {%4,%5,%6,%7}, {%8,%9}, {%0,%1,%2,%3};"
                        : "+f"(c[0]), "+f"(c[1]), "+f"(c[2]), "+f"(c[3])
                        : "r"(al[mt][0]), "r"(al[mt][1]), "r"(al[mt][2]), "r"(al[mt][3]),
                          "r"(bh0), "r"(bh1));
                }
            }
        }
    }

    #pragma unroll
    for (int mt = 0; mt < 2; mt++) {
        int r0 = m0 + warp_m + mt * 16 + (lane >> 2);
        int r1 = r0 + 8;
        float d0 = (r0 < N_NODES) ? g_dinv[r0] : 0.0f;
        float d1 = (r1 < N_NODES) ? g_dinv[r1] : 0.0f;
        #pragma unroll
        for (int nt = 0; nt < 8; nt++) {
            int cc = warp_n + nt * 8 + (lane & 3) * 2;
            if (r0 < N_NODES) {
                float2 o = make_float2(acc[mt][nt][0] * d0, acc[mt][nt][1] * d0);
                *(float2*)&g_hs[(size_t)r0 * D_H + cc] = o;
            }
            if (r1 < N_NODES) {
                float2 o = make_float2(acc[mt][nt][2] * d1, acc[mt][nt][3] * d1);
                *(float2*)&g_hs[(size_t)r1 * D_H + cc] = o;
            }
        }
    }
}

// ---------------- agg1: CSR gather, warp per node, float4 lanes ------------
__global__ void __launch_bounds__(256) agg1_kernel() {
    int w = (blockIdx.x * blockDim.x + threadIdx.x) >> 5;
    int lane = threadIdx.x & 31;
    if (w >= N_NODES) return;
    int start = g_off[w];
    int cnt   = g_cnt[w];
    const float* base = &g_hs[(size_t)lane * 4];
    float4 acc = *(const float4*)&g_hs[(size_t)w * D_H + lane * 4];

    for (int b = 0; b < cnt; b += 32) {
        int n = min(32, cnt - b);
        int src = (lane < n) ? g_cse[start + b + lane].x : 0;
        int j = 0;
        for (; j + 4 <= n; j += 4) {
            int s0 = __shfl_sync(0xffffffffu, src, j);
            int s1 = __shfl_sync(0xffffffffu, src, j + 1);
            int s2 = __shfl_sync(0xffffffffu, src, j + 2);
            int s3 = __shfl_sync(0xffffffffu, src, j + 3);
            float4 v0 = *(const float4*)(base + (size_t)s0 * D_H);
            float4 v1 = *(const float4*)(base + (size_t)s1 * D_H);
            float4 v2 = *(const float4*)(base + (size_t)s2 * D_H);
            float4 v3 = *(const float4*)(base + (size_t)s3 * D_H);
            acc.x += (v0.x + v1.x) + (v2.x + v3.x);
            acc.y += (v0.y + v1.y) + (v2.y + v3.y);
            acc.z += (v0.z + v1.z) + (v2.z + v3.z);
            acc.w += (v0.w + v1.w) + (v2.w + v3.w);
        }
        for (; j < n; j++) {
            int s = __shfl_sync(0xffffffffu, src, j);
            float4 v = *(const float4*)(base + (size_t)s * D_H);
            acc.x += v.x; acc.y += v.y; acc.z += v.z; acc.w += v.w;
        }
    }
    *(float4*)&g_acc1[(size_t)w * D_H + lane * 4] = acc;
}

// ---------------- GEMM2 (mma.sync bf16 hi/lo): hs2 = (relu(...) @ W2)*dinv -
__global__ void __launch_bounds__(256) gemm2_mma_kernel(const float* __restrict__ b1) {
    __shared__ __align__(16) uint8_t Ahi[128 * 128];
    __shared__ __align__(16) uint8_t Alo[128 * 128];

    const int tid  = threadIdx.x;
    const int wid  = tid >> 5;
    const int lane = tid & 31;
    const int m0   = blockIdx.x * 128;
    const int warp_m = (wid >> 1) * 32;
    const int warp_n = (wid & 1) * 32;     // N=64 split across 2 warps

    const uint32_t ahi_base = smem_u32(Ahi);
    const uint32_t alo_base = smem_u32(Alo);

    const int arow  = tid >> 1;
    const int ahalf = tid & 1;
    const int gm    = m0 + arow;
    const bool rok = (gm < N_NODES);
    const float dA = rok ? g_dinv[gm] : 0.0f;
    const float* arowp = g_acc1 + (size_t)gm * D_H;

    float acc[2][4][4];
    #pragma unroll
    for (int mt = 0; mt < 2; mt++)
        #pragma unroll
        for (int nt = 0; nt < 4; nt++)
            #pragma unroll
            for (int r = 0; r < 4; r++) acc[mt][nt][r] = 0.0f;

    for (int chunk = 0; chunk < 2; chunk++) {
        if (chunk > 0) __syncthreads();
        #pragma unroll
        for (int q = 0; q < 8; q++) {
            int kl = ahalf * 32 + q * 4;
            int kg = chunk * 64 + kl;
            float4 v = make_float4(0.f, 0.f, 0.f, 0.f);
            if (rok) {
                float4 a = *(const float4*)(arowp + kg);
                float4 bb = *(const float4*)(b1 + kg);
                v.x = fmaxf(fmaf(a.x, dA, bb.x), 0.0f);
                v.y = fmaxf(fmaf(a.y, dA, bb.y), 0.0f);
                v.z = fmaxf(fmaf(a.z, dA, bb.z), 0.0f);
                v.w = fmaxf(fmaf(a.w, dA, bb.w), 0.0f);
            }
            __nv_bfloat16 h0 = __float2bfloat16(v.x);
            __nv_bfloat16 h1 = __float2bfloat16(v.y);
            __nv_bfloat16 h2 = __float2bfloat16(v.z);
            __nv_bfloat16 h3 = __float2bfloat16(v.w);
            __nv_bfloat16 l0 = __float2bfloat16(v.x - __bfloat162float(h0));
            __nv_bfloat16 l1 = __float2bfloat16(v.y - __bfloat162float(h1));
            __nv_bfloat16 l2 = __float2bfloat16(v.z - __bfloat162float(h2));
            __nv_bfloat16 l3 = __float2bfloat16(v.w - __bfloat162float(h3));
            int ch  = kl >> 3;
            int sub = (kl & 7) ? 8 : 0;
            uint32_t off = arow * 128 + ((ch ^ (arow & 7)) << 4) + sub;
            __nv_bfloat162 hp0 = {h0, h1}, hp1 = {h2, h3};
            __nv_bfloat162 lp0 = {l0, l1}, lp1 = {l2, l3};
            uint2 hv = { *(uint32_t*)&hp0, *(uint32_t*)&hp1 };
            uint2 lv = { *(uint32_t*)&lp0, *(uint32_t*)&lp1 };
            *(uint2*)(Ahi + off) = hv;
            *(uint2*)(Alo + off) = lv;
        }
        __syncthreads();

        #pragma unroll
        for (int kstep = 0; kstep < 4; kstep++) {
            int kg = chunk * 4 + kstep;
            uint32_t ah[2][4], al[2][4];
            #pragma unroll
            for (int mt = 0; mt < 2; mt++) {
                int mrow = warp_m + mt * 16 + (lane & 7) + ((lane & 8) ? 8 : 0);
                int ch   = kstep * 2 + (lane >> 4);
                uint32_t off = mrow * 128 + ((ch ^ (mrow & 7)) << 4);
                asm volatile("ldmatrix.sync.aligned.m8n8.x4.shared.b16 {%0,%1,%2,%3}, [%4];"
                             : "=r"(ah[mt][0]), "=r"(ah[mt][1]), "=r"(ah[mt][2]), "=r"(ah[mt][3])
                             : "r"(ahi_base + off));
                asm volatile("ldmatrix.sync.aligned.m8n8.x4.shared.b16 {%0,%1,%2,%3}, [%4];"
                             : "=r"(al[mt][0]), "=r"(al[mt][1]), "=r"(al[mt][2]), "=r"(al[mt][3])
                             : "r"(alo_base + off));
            }
            uint4 bh[2], bl[2];
            #pragma unroll
            for (int p = 0; p < 2; p++) {
                int npair = (warp_n >> 4) + p;
                int idx = kg * 512 + npair * 128 + lane * 4;
                bh[p] = *(const uint4*)(g_b2hi + idx);
                bl[p] = *(const uint4*)(g_b2lo + idx);
            }
            #pragma unroll
            for (int mt = 0; mt < 2; mt++) {
                #pragma unroll
                for (int nt = 0; nt < 4; nt++) {
                    int p = nt >> 1;
                    uint32_t bh0 = (nt & 1) ? bh[p].z : bh[p].x;
                    uint32_t bh1 = (nt & 1) ? bh[p].w : bh[p].y;
                    uint32_t bl0 = (nt & 1) ? bl[p].z : bl[p].x;
                    uint32_t bl1 = (nt & 1) ? bl[p].w : bl[p].y;
                    float* c = acc[mt][nt];
                    asm volatile("mma.sync.aligned.m16n8k16.row.col.f32.bf16.bf16.f32 "
                        "{%0,%1,%2,%3}, {%4,%5,%6,%7}, {%8,%9}, {%0,%1,%2,%3};"
                        : "+f"(c[0]), "+f"(c[1]), "+f"(c[2]), "+f"(c[3])
                        : "r"(ah[mt][0]), "r"(ah[mt][1]), "r"(ah[mt][2]), "r"(ah[mt][3]),
                          "r"(bh0), "r"(bh1));
                    asm volatile("mma.sync.aligned.m16n8k16.row.col.f32.bf16.bf16.f32 "
                        "{%0,%1,%2,%3}, {%4,%5,%6,%7}, {%8,%9}, {%0,%1,%2,%3};"
                        : "+f"(c[0]), "+f"(c[1]), "+f"(c[2]), "+f"(c[3])
                        : "r"(ah[mt][0]), "r"(ah[mt][1]), "r"(ah[mt][2]), "r"(ah[mt][3]),
                          "r"(bl0), "r"(bl1));
                    asm volatile("mma.sync.aligned.m16n8k16.row.col.f32.bf16.bf16.f32 "
                        "{%0,%1,%2,%3}, {%4,%5,%6,%7}, {%8,%9}, {%0,%1,%2,%3};"
                        : "+f"(c[0]), "+f"(c[1]), "+f"(c[2]), "+f"(c[3])
                        : "r"(al[mt][0]), "r"(al[mt][1]), "r"(al[mt][2]), "r"(al[mt][3]),
                          "r"(bh0), "r"(bh1));
                }
            }
        }
    }

    #pragma unroll
    for (int mt = 0; mt < 2; mt++) {
        int r0 = m0 + warp_m + mt * 16 + (lane >> 2);
        int r1 = r0 + 8;
        float d0 = (r0 < N_NODES) ? g_dinv[r0] : 0.0f;
        float d1 = (r1 < N_NODES) ? g_dinv[r1] : 0.0f;
        #pragma unroll
        for (int nt = 0; nt < 4; nt++) {
            int cc = warp_n + nt * 8 + (lane & 3) * 2;
            if (r0 < N_NODES) {
                float2 o = make_float2(acc[mt][nt][0] * d0, acc[mt][nt][1] * d0);
                *(float2*)&g_hs2[(size_t)r0 * D_O + cc] = o;
            }
            if (r1 < N_NODES) {
                float2 o = make_float2(acc[mt][nt][2] * d1, acc[mt][nt][3] * d1);
                *(float2*)&g_hs2[(size_t)r1 * D_O + cc] = o;
            }
        }
    }
}

// ---------------- agg2: CSR gather, warp per node, float2 lanes ------------
__global__ void __launch_bounds__(256) agg2_kernel(const float* __restrict__ b2) {
    int w = (blockIdx.x * blockDim.x + threadIdx.x) >> 5;
    int lane = threadIdx.x & 31;
    if (w >= N_NODES) return;
    int start = g_off[w];
    int cnt   = g_cnt[w];
    const float* base = &g_hs2[(size_t)lane * 2];
    float2 acc = *(const float2*)&g_hs2[(size_t)w * D_O + lane * 2];

    for (int b = 0; b < cnt; b += 32) {
        int n = min(32, cnt - b);
        int src = (lane < n) ? g_cse[start + b + lane].x : 0;
        int j = 0;
        for (; j + 4 <= n; j += 4) {
            int s0 = __shfl_sync(0xffffffffu, src, j);
            int s1 = __shfl_sync(0xffffffffu, src, j + 1);
            int s2 = __shfl_sync(0xffffffffu, src, j + 2);
            int s3 = __shfl_sync(0xffffffffu, src, j + 3);
            float2 v0 = *(const float2*)(base + (size_t)s0 * D_O);
            float2 v1 = *(const float2*)(base + (size_t)s1 * D_O);
            float2 v2 = *(const float2*)(base + (size_t)s2 * D_O);
            float2 v3 = *(const float2*)(base + (size_t)s3 * D_O);
            acc.x += (v0.x + v1.x) + (v2.x + v3.x);
            acc.y += (v0.y + v1.y) + (v2.y + v3.y);
        }
        for (; j < n; j++) {
            int s = __shfl_sync(0xffffffffu, src, j);
            float2 v = *(const float2*)(base + (size_t)s * D_O);
            acc.x += v.x; acc.y += v.y;
        }
    }
    float d = g_dinv[w];
    float2 z = make_float2(fmaf(acc.x, d, b2[lane * 2]),
                           fmaf(acc.y, d, b2[lane * 2 + 1]));
    *(float2*)&g_z[(size_t)w * D_O + lane * 2] = z;
}

// ---------------- decode (CSR order): warp per dst node -------------------
__global__ void __launch_bounds__(256) decode_csr_kernel(float* __restrict__ out) {
    int w = (blockIdx.x * blockDim.x + threadIdx.x) >> 5;
    int lane = threadIdx.x & 31;
    if (w >= N_NODES) return;
    int start = g_off[w];
    int cnt   = g_cnt[w];
    if (cnt == 0) return;
    int half = lane >> 4;
    int hl   = lane & 15;

    float4 zc = *(const float4*)&g_z[(size_t)w * D_O + hl * 4];

    for (int b = 0; b < cnt; b += 2) {
        int idx = b + half;
        float s = 0.0f;
        int eid = 0;
        bool ok = (idx < cnt);
        if (ok) {
            int2 se = g_cse[start + idx];
            eid = se.y;
            float4 zr = *(const float4*)&g_z[(size_t)se.x * D_O + hl * 4];
            s = zc.x * zr.x + zc.y * zr.y + zc.z * zr.z + zc.w * zr.w;
        }
        s += __shfl_xor_sync(0xffffffffu, s, 1);
        s += __shfl_xor_sync(0xffffffffu, s, 2);
        s += __shfl_xor_sync(0xffffffffu, s, 4);
        s += __shfl_xor_sync(0xffffffffu, s, 8);
        if (ok && hl == 0) out[eid] = s;
    }
}

// ---------------- launch ----------------
extern "C" void kernel_launch(void* const* d_in, const int* in_sizes, int n_in,
                              void* d_out, int out_size) {
    const float* x  = (const float*)d_in[0];
    const float* W1 = (const float*)d_in[1];
    const float* b1 = (const float*)d_in[2];
    const float* W2 = (const float*)d_in[3];
    const float* b2 = (const float*)d_in[4];
    const int*   ei = (const int*)d_in[5];
    const int E = in_sizes[5] / 2;

    static cudaStream_t s2 = nullptr;
    static cudaEvent_t evFork = nullptr, evDinv = nullptr, evCsr = nullptr;
    if (!s2) {
        cudaStreamCreateWithFlags(&s2, cudaStreamNonBlocking);
        cudaEventCreateWithFlags(&evFork, cudaEventDisableTiming);
        cudaEventCreateWithFlags(&evDinv, cudaEventDisableTiming);
        cudaEventCreateWithFlags(&evCsr,  cudaEventDisableTiming);
    }

    // fork: CSR chain on s2
    cudaEventRecord(evFork, 0);
    cudaStreamWaitEvent(s2, evFork, 0);

    cnt_init_kernel<<<NB1, 256, 0, s2>>>();
    deg_count_kernel<<<(E + 255) / 256, 256, 0, s2>>>(ei + E, E);
    dinv_kernel<<<NB1, 256, 0, s2>>>();
    cudaEventRecord(evDinv, s2);
    scan1_kernel<<<NB1, 256, 0, s2>>>();
    scan2_kernel<<<1, 512, 0, s2>>>();
    scan3b_kernel<<<NB1, 256, 0, s2>>>();
    csr_fill_kernel<<<(E + 255) / 256, 256, 0, s2>>>(ei, E);
    cudaEventRecord(evCsr, s2);

    // main stream: W prep (independent), then gemm1 (needs dinv only)
    w1split_kernel<<<128, 256>>>(W1);
    w2split_kernel<<<16, 256>>>(W2);
    cudaStreamWaitEvent(0, evDinv, 0);
    gemm1_mma_kernel<<<(N_NODES + 127) / 128, 256>>>(x);

    // join: aggregation needs CSR
    cudaStreamWaitEvent(0, evCsr, 0);
    agg1_kernel<<<(N_NODES * 32 + 255) / 256, 256>>>();

    gemm2_mma_kernel<<<(N_NODES + 127) / 128, 256>>>(b1);
    agg2_kernel<<<(N_NODES * 32 + 255) / 256, 256>>>(b2);

    decode_csr_kernel<<<(N_NODES * 32 + 255) / 256, 256>>>((float*)d_out);
}